// round 1
// baseline (speedup 1.0000x reference)
#include <cuda_runtime.h>
#include <cuda_bf16.h>
#include <math.h>

// ---------------- problem constants ----------------
#define LAYERS 12
#define HEADS  12
#define CDIM   768
#define TSEQ   1024
#define BATCH  4
#define MROWS  (BATCH*TSEQ)      // 4096
#define C3     (3*CDIM)          // 2304
#define C4     (4*CDIM)          // 3072
#define DHEAD  64

// ---------------- scratch (device globals: no allocation allowed) ----------
__device__ float g_x  [MROWS*CDIM];
__device__ float g_h  [MROWS*CDIM];
__device__ float g_qkv[MROWS*C3];
__device__ float g_y  [MROWS*CDIM];
__device__ float g_fc [MROWS*C4];

// ---------------- embedding ----------------
__global__ __launch_bounds__(256) void embed_kernel(
    const int* __restrict__ idx, const float* __restrict__ wte,
    const float* __restrict__ wpe, float* __restrict__ x)
{
    int i = blockIdx.x * 256 + threadIdx.x;          // over MROWS*CDIM
    int row = i / CDIM;
    int c   = i - row * CDIM;
    int t   = row & (TSEQ - 1);
    int id  = idx[row];
    x[i] = wte[(size_t)id * CDIM + c] + wpe[(size_t)t * CDIM + c];
}

// ---------------- layernorm ----------------
__global__ __launch_bounds__(256) void ln_kernel(
    const float* __restrict__ x, const float* __restrict__ w,
    const float* __restrict__ b, float* __restrict__ out)
{
    int row = blockIdx.x;
    const float* xr = x + (size_t)row * CDIM;
    float s = 0.f, s2 = 0.f;
    for (int i = threadIdx.x; i < CDIM; i += 256) {
        float v = xr[i]; s += v; s2 += v * v;
    }
    #pragma unroll
    for (int o = 16; o; o >>= 1) {
        s  += __shfl_xor_sync(0xffffffffu, s,  o);
        s2 += __shfl_xor_sync(0xffffffffu, s2, o);
    }
    __shared__ float rbuf[16];
    int wid = threadIdx.x >> 5, lane = threadIdx.x & 31;
    if (lane == 0) { rbuf[wid] = s; rbuf[8 + wid] = s2; }
    __syncthreads();
    float ts = 0.f, ts2 = 0.f;
    #pragma unroll
    for (int i = 0; i < 8; i++) { ts += rbuf[i]; ts2 += rbuf[8 + i]; }
    float mu  = ts * (1.0f / CDIM);
    float var = ts2 * (1.0f / CDIM) - mu * mu;
    float rs  = rsqrtf(var + 1e-5f);
    float* orow = out + (size_t)row * CDIM;
    for (int i = threadIdx.x; i < CDIM; i += 256) {
        orow[i] = (xr[i] - mu) * rs * w[i] + b[i];
    }
}

// ---------------- final LN + head matvec ----------------
__global__ __launch_bounds__(256) void head_kernel(
    const float* __restrict__ x, const float* __restrict__ lw,
    const float* __restrict__ lb, const float* __restrict__ wh,
    float* __restrict__ out)
{
    int row = blockIdx.x;
    const float* xr = x + (size_t)row * CDIM;
    float s = 0.f, s2 = 0.f;
    for (int i = threadIdx.x; i < CDIM; i += 256) {
        float v = xr[i]; s += v; s2 += v * v;
    }
    #pragma unroll
    for (int o = 16; o; o >>= 1) {
        s  += __shfl_xor_sync(0xffffffffu, s,  o);
        s2 += __shfl_xor_sync(0xffffffffu, s2, o);
    }
    __shared__ float rbuf[16];
    int wid = threadIdx.x >> 5, lane = threadIdx.x & 31;
    if (lane == 0) { rbuf[wid] = s; rbuf[8 + wid] = s2; }
    __syncthreads();
    float ts = 0.f, ts2 = 0.f;
    #pragma unroll
    for (int i = 0; i < 8; i++) { ts += rbuf[i]; ts2 += rbuf[8 + i]; }
    float mu  = ts * (1.0f / CDIM);
    float var = ts2 * (1.0f / CDIM) - mu * mu;
    float rs  = rsqrtf(var + 1e-5f);

    float acc = 0.f;
    for (int i = threadIdx.x; i < CDIM; i += 256) {
        float hn = (xr[i] - mu) * rs * lw[i] + lb[i];
        acc += hn * wh[i];
    }
    #pragma unroll
    for (int o = 16; o; o >>= 1) acc += __shfl_xor_sync(0xffffffffu, acc, o);
    __syncthreads();
    if (lane == 0) rbuf[wid] = acc;
    __syncthreads();
    if (threadIdx.x == 0) {
        float t = 0.f;
        #pragma unroll
        for (int i = 0; i < 8; i++) t += rbuf[i];
        out[row] = t;
    }
}

// ---------------- SGEMM 128x128x8, 256 threads, 8x8 per thread --------------
// EPI: 0 = +bias, 1 = +bias +residual, 2 = +bias then tanh-GELU
#define BM 128
#define BN 128
#define BK 8

__device__ __forceinline__ float gelu_tanh(float v) {
    float c = 0.7978845608028654f * (v + 0.044715f * v * v * v);
    return 0.5f * v * (1.0f + tanhf(c));
}

template <int EPI>
__global__ __launch_bounds__(256) void sgemm_kernel(
    const float* __restrict__ A, const float* __restrict__ B,
    const float* __restrict__ bias, const float* __restrict__ R,
    float* __restrict__ C, int M, int N, int K)
{
    __shared__ float As[BK][BM];
    __shared__ float Bs[BK][BN];

    int tid = threadIdx.x;
    int bm = blockIdx.y, bn = blockIdx.x;

    int a_row = tid >> 1;
    int a_col = (tid & 1) * 4;
    int b_row = tid >> 5;
    int b_col = (tid & 31) * 4;

    const float* Ablk = A + (size_t)(bm * BM) * K;
    const float* Bblk = B + bn * BN;

    int tx = tid & 15, ty = tid >> 4;
    float acc[8][8];
    #pragma unroll
    for (int i = 0; i < 8; i++)
        #pragma unroll
        for (int j = 0; j < 8; j++) acc[i][j] = 0.f;

    for (int k0 = 0; k0 < K; k0 += BK) {
        float4 av = *(const float4*)(Ablk + (size_t)a_row * K + k0 + a_col);
        float4 bv = *(const float4*)(Bblk + (size_t)(k0 + b_row) * N + b_col);
        As[a_col + 0][a_row] = av.x;
        As[a_col + 1][a_row] = av.y;
        As[a_col + 2][a_row] = av.z;
        As[a_col + 3][a_row] = av.w;
        *(float4*)&Bs[b_row][b_col] = bv;
        __syncthreads();

        #pragma unroll
        for (int k = 0; k < BK; k++) {
            float4 a0 = *(const float4*)&As[k][ty * 4];
            float4 a1 = *(const float4*)&As[k][64 + ty * 4];
            float4 b0 = *(const float4*)&Bs[k][tx * 4];
            float4 b1 = *(const float4*)&Bs[k][64 + tx * 4];
            float ra[8] = {a0.x, a0.y, a0.z, a0.w, a1.x, a1.y, a1.z, a1.w};
            float rb[8] = {b0.x, b0.y, b0.z, b0.w, b1.x, b1.y, b1.z, b1.w};
            #pragma unroll
            for (int i = 0; i < 8; i++)
                #pragma unroll
                for (int j = 0; j < 8; j++)
                    acc[i][j] += ra[i] * rb[j];
        }
        __syncthreads();
    }

    // epilogue
    #pragma unroll
    for (int i = 0; i < 8; i++) {
        int m = bm * BM + ty * 4 + (i < 4 ? i : 60 + i);
        #pragma unroll
        for (int jj = 0; jj < 2; jj++) {
            int n = bn * BN + tx * 4 + jj * 64;
            float4 v;
            v.x = acc[i][jj * 4 + 0];
            v.y = acc[i][jj * 4 + 1];
            v.z = acc[i][jj * 4 + 2];
            v.w = acc[i][jj * 4 + 3];
            float4 bb = *(const float4*)(bias + n);
            v.x += bb.x; v.y += bb.y; v.z += bb.z; v.w += bb.w;
            if (EPI == 1) {
                float4 r = *(const float4*)(R + (size_t)m * N + n);
                v.x += r.x; v.y += r.y; v.z += r.z; v.w += r.w;
            } else if (EPI == 2) {
                v.x = gelu_tanh(v.x); v.y = gelu_tanh(v.y);
                v.z = gelu_tanh(v.z); v.w = gelu_tanh(v.w);
            }
            *(float4*)(C + (size_t)m * N + n) = v;
        }
    }
}

// ---------------- flash attention (fp32, causal) ----------------
// grid: (T/64, B*H); block 256. thread: qr = tid/4, seg = tid%4.
// thread owns S cols kc = seg*16 + j (j=0..15) and O dims d = seg*16 + i.
__global__ __launch_bounds__(256) void attn_kernel(
    const float* __restrict__ qkv, float* __restrict__ y)
{
    extern __shared__ float sm[];
    float* Qs  = sm;                 // [64][65]
    float* Kts = Qs  + 64 * 65;      // [64 d][68] -> (d,kc) at d*68+kc
    float* Vs  = Kts + 64 * 68;      // [64 kc][68] -> (kc,d) at kc*68+d
    float* Ss  = Vs  + 64 * 68;      // [64 qr][68]

    int tid = threadIdx.x;
    int qt = blockIdx.x;             // 0..15
    int bh = blockIdx.y;             // 0..47
    int b = bh / HEADS, h = bh - (bh / HEADS) * HEADS;

    size_t rowbase = (size_t)b * TSEQ;
    int qoff = h * DHEAD;
    int koff = CDIM + h * DHEAD;
    int voff = 2 * CDIM + h * DHEAD;

    int lc  = (tid & 15) * 4;        // 0..60, column quad within head dim
    int lr0 = tid >> 4;              // 0..15

    // load Q tile (rows qt*64..+63)
    #pragma unroll
    for (int rr = lr0; rr < 64; rr += 16) {
        float4 v = *(const float4*)(qkv + (rowbase + qt * 64 + rr) * C3 + qoff + lc);
        Qs[rr * 65 + lc + 0] = v.x;
        Qs[rr * 65 + lc + 1] = v.y;
        Qs[rr * 65 + lc + 2] = v.z;
        Qs[rr * 65 + lc + 3] = v.w;
    }

    int qr  = tid >> 2;
    int seg = tid & 3;
    int qg  = qt * 64 + qr;

    float m_i = -1e30f, l_i = 0.f;
    float O[16];
    #pragma unroll
    for (int i = 0; i < 16; i++) O[i] = 0.f;

    const float scale = 0.125f;      // 1/sqrt(64)

    for (int kt = 0; kt <= qt; kt++) {
        // load K (transposed) and V tiles
        #pragma unroll
        for (int rr = lr0; rr < 64; rr += 16) {
            const float* base = qkv + (rowbase + kt * 64 + rr) * C3;
            float4 kv = *(const float4*)(base + koff + lc);
            Kts[(lc + 0) * 68 + rr] = kv.x;
            Kts[(lc + 1) * 68 + rr] = kv.y;
            Kts[(lc + 2) * 68 + rr] = kv.z;
            Kts[(lc + 3) * 68 + rr] = kv.w;
            float4 vv = *(const float4*)(base + voff + lc);
            Vs[rr * 68 + lc + 0] = vv.x;
            Vs[rr * 68 + lc + 1] = vv.y;
            Vs[rr * 68 + lc + 2] = vv.z;
            Vs[rr * 68 + lc + 3] = vv.w;
        }
        __syncthreads();

        // S = Q K^T for this thread's 16 key columns
        float sacc[16];
        #pragma unroll
        for (int j = 0; j < 16; j++) sacc[j] = 0.f;
        const float* KtsBase = Kts + seg * 16;
        const float* Qrow = Qs + qr * 65;
        #pragma unroll 8
        for (int d = 0; d < 64; d++) {
            float qv = Qrow[d];
            float4 k0 = *(const float4*)(KtsBase + d * 68 + 0);
            float4 k1 = *(const float4*)(KtsBase + d * 68 + 4);
            float4 k2 = *(const float4*)(KtsBase + d * 68 + 8);
            float4 k3 = *(const float4*)(KtsBase + d * 68 + 12);
            sacc[0]  += qv * k0.x; sacc[1]  += qv * k0.y;
            sacc[2]  += qv * k0.z; sacc[3]  += qv * k0.w;
            sacc[4]  += qv * k1.x; sacc[5]  += qv * k1.y;
            sacc[6]  += qv * k1.z; sacc[7]  += qv * k1.w;
            sacc[8]  += qv * k2.x; sacc[9]  += qv * k2.y;
            sacc[10] += qv * k2.z; sacc[11] += qv * k2.w;
            sacc[12] += qv * k3.x; sacc[13] += qv * k3.y;
            sacc[14] += qv * k3.z; sacc[15] += qv * k3.w;
        }

        float mblk = -1e30f;
        #pragma unroll
        for (int j = 0; j < 16; j++) {
            int kg = kt * 64 + seg * 16 + j;
            float s = sacc[j] * scale;
            if (kg > qg) s = -1e30f;
            sacc[j] = s;
            mblk = fmaxf(mblk, s);
        }
        mblk = fmaxf(mblk, __shfl_xor_sync(0xffffffffu, mblk, 1));
        mblk = fmaxf(mblk, __shfl_xor_sync(0xffffffffu, mblk, 2));
        float m_new = fmaxf(m_i, mblk);
        float alpha = __expf(m_i - m_new);
        float lblk = 0.f;
        #pragma unroll
        for (int j = 0; j < 16; j++) {
            float p = __expf(sacc[j] - m_new);
            sacc[j] = p;
            lblk += p;
        }
        lblk += __shfl_xor_sync(0xffffffffu, lblk, 1);
        lblk += __shfl_xor_sync(0xffffffffu, lblk, 2);
        l_i = l_i * alpha + lblk;
        m_i = m_new;

        #pragma unroll
        for (int j = 0; j < 16; j++)
            Ss[qr * 68 + seg * 16 + j] = sacc[j];
        __syncthreads();

        // O = O*alpha + P @ V
        #pragma unroll
        for (int i = 0; i < 16; i++) O[i] *= alpha;
        const float* VsBase = Vs + seg * 16;
        const float* Srow = Ss + qr * 68;
        #pragma unroll 4
        for (int j = 0; j < 64; j++) {
            float s = Srow[j];
            float4 v0 = *(const float4*)(VsBase + j * 68 + 0);
            float4 v1 = *(const float4*)(VsBase + j * 68 + 4);
            float4 v2 = *(const float4*)(VsBase + j * 68 + 8);
            float4 v3 = *(const float4*)(VsBase + j * 68 + 12);
            O[0]  += s * v0.x; O[1]  += s * v0.y; O[2]  += s * v0.z; O[3]  += s * v0.w;
            O[4]  += s * v1.x; O[5]  += s * v1.y; O[6]  += s * v1.z; O[7]  += s * v1.w;
            O[8]  += s * v2.x; O[9]  += s * v2.y; O[10] += s * v2.z; O[11] += s * v2.w;
            O[12] += s * v3.x; O[13] += s * v3.y; O[14] += s * v3.z; O[15] += s * v3.w;
        }
        __syncthreads();
    }

    float inv = 1.f / l_i;
    float* yrow = y + (rowbase + qt * 64 + qr) * CDIM + h * DHEAD + seg * 16;
    #pragma unroll
    for (int q4 = 0; q4 < 4; q4++) {
        float4 v;
        v.x = O[q4 * 4 + 0] * inv;
        v.y = O[q4 * 4 + 1] * inv;
        v.z = O[q4 * 4 + 2] * inv;
        v.w = O[q4 * 4 + 3] * inv;
        *(float4*)(yrow + q4 * 4) = v;
    }
}

// ---------------- launch ----------------
extern "C" void kernel_launch(void* const* d_in, const int* in_sizes, int n_in,
                              void* d_out, int out_size)
{
    const int*   idx    = (const int*)  d_in[0];
    const float* wte    = (const float*)d_in[1];
    const float* wpe    = (const float*)d_in[2];
    const float* ln1_w  = (const float*)d_in[3];
    const float* ln1_b  = (const float*)d_in[4];
    const float* w_qkv  = (const float*)d_in[5];
    const float* b_qkv  = (const float*)d_in[6];
    const float* w_ao   = (const float*)d_in[7];
    const float* b_ao   = (const float*)d_in[8];
    const float* ln2_w  = (const float*)d_in[9];
    const float* ln2_b  = (const float*)d_in[10];
    const float* w_fc   = (const float*)d_in[11];
    const float* b_fc   = (const float*)d_in[12];
    const float* w_fp   = (const float*)d_in[13];
    const float* b_fp   = (const float*)d_in[14];
    const float* lnf_w  = (const float*)d_in[15];
    const float* lnf_b  = (const float*)d_in[16];
    const float* w_head = (const float*)d_in[17];
    float* out = (float*)d_out;

    float *x, *h, *qkvb, *yb, *fcb;
    cudaGetSymbolAddress((void**)&x,    g_x);
    cudaGetSymbolAddress((void**)&h,    g_h);
    cudaGetSymbolAddress((void**)&qkvb, g_qkv);
    cudaGetSymbolAddress((void**)&yb,   g_y);
    cudaGetSymbolAddress((void**)&fcb,  g_fc);

    const int attn_smem = (64 * 65 + 64 * 68 + 64 * 68 + 64 * 68) * sizeof(float);
    cudaFuncSetAttribute(attn_kernel, cudaFuncAttributeMaxDynamicSharedMemorySize, attn_smem);

    // embedding
    embed_kernel<<<(MROWS * CDIM) / 256, 256>>>(idx, wte, wpe, x);

    for (int l = 0; l < LAYERS; l++) {
        // LN1
        ln_kernel<<<MROWS, 256>>>(x, ln1_w + l * CDIM, ln1_b + l * CDIM, h);
        // QKV = h @ w_qkv + b
        sgemm_kernel<0><<<dim3(C3 / BN, MROWS / BM), 256>>>(
            h, w_qkv + (size_t)l * CDIM * C3, b_qkv + l * C3, nullptr, qkvb,
            MROWS, C3, CDIM);
        // attention
        attn_kernel<<<dim3(TSEQ / 64, BATCH * HEADS), 256, attn_smem>>>(qkvb, yb);
        // x = x + y @ w_ao + b
        sgemm_kernel<1><<<dim3(CDIM / BN, MROWS / BM), 256>>>(
            yb, w_ao + (size_t)l * CDIM * CDIM, b_ao + l * CDIM, x, x,
            MROWS, CDIM, CDIM);
        // LN2
        ln_kernel<<<MROWS, 256>>>(x, ln2_w + l * CDIM, ln2_b + l * CDIM, h);
        // fc = gelu(h @ w_fc + b)
        sgemm_kernel<2><<<dim3(C4 / BN, MROWS / BM), 256>>>(
            h, w_fc + (size_t)l * CDIM * C4, b_fc + l * C4, nullptr, fcb,
            MROWS, C4, CDIM);
        // x = x + fc @ w_fp + b
        sgemm_kernel<1><<<dim3(CDIM / BN, MROWS / BM), 256>>>(
            fcb, w_fp + (size_t)l * C4 * CDIM, b_fp + l * CDIM, x, x,
            MROWS, CDIM, C4);
    }

    // final LN + head
    head_kernel<<<MROWS, 256>>>(x, lnf_w, lnf_b, w_head, out);
}

// round 2
// speedup vs baseline: 1.6638x; 1.6638x over previous
#include <cuda_runtime.h>
#include <cuda_bf16.h>
#include <math.h>

// ---------------- problem constants ----------------
#define LAYERS 12
#define HEADS  12
#define CDIM   768
#define TSEQ   1024
#define BATCH  4
#define MROWS  (BATCH*TSEQ)      // 4096
#define C3     (3*CDIM)          // 2304
#define C4     (4*CDIM)          // 3072
#define DHEAD  64

// ---------------- scratch (device globals: no allocation allowed) ----------
__device__ float g_x  [MROWS*CDIM];
__device__ float g_h  [MROWS*CDIM];
__device__ float g_qkv[MROWS*C3];
__device__ float g_y  [MROWS*CDIM];
__device__ float g_fc [MROWS*C4];

// ---------------- embedding ----------------
__global__ __launch_bounds__(256) void embed_kernel(
    const int* __restrict__ idx, const float* __restrict__ wte,
    const float* __restrict__ wpe, float* __restrict__ x)
{
    int i = blockIdx.x * 256 + threadIdx.x;          // over MROWS*CDIM
    int row = i / CDIM;
    int c   = i - row * CDIM;
    int t   = row & (TSEQ - 1);
    int id  = idx[row];
    x[i] = wte[(size_t)id * CDIM + c] + wpe[(size_t)t * CDIM + c];
}

// ---------------- layernorm ----------------
__global__ __launch_bounds__(256) void ln_kernel(
    const float* __restrict__ x, const float* __restrict__ w,
    const float* __restrict__ b, float* __restrict__ out)
{
    int row = blockIdx.x;
    const float* xr = x + (size_t)row * CDIM;
    float s = 0.f, s2 = 0.f;
    for (int i = threadIdx.x; i < CDIM; i += 256) {
        float v = xr[i]; s += v; s2 += v * v;
    }
    #pragma unroll
    for (int o = 16; o; o >>= 1) {
        s  += __shfl_xor_sync(0xffffffffu, s,  o);
        s2 += __shfl_xor_sync(0xffffffffu, s2, o);
    }
    __shared__ float rbuf[16];
    int wid = threadIdx.x >> 5, lane = threadIdx.x & 31;
    if (lane == 0) { rbuf[wid] = s; rbuf[8 + wid] = s2; }
    __syncthreads();
    float ts = 0.f, ts2 = 0.f;
    #pragma unroll
    for (int i = 0; i < 8; i++) { ts += rbuf[i]; ts2 += rbuf[8 + i]; }
    float mu  = ts * (1.0f / CDIM);
    float var = ts2 * (1.0f / CDIM) - mu * mu;
    float rs  = rsqrtf(var + 1e-5f);
    float* orow = out + (size_t)row * CDIM;
    for (int i = threadIdx.x; i < CDIM; i += 256) {
        orow[i] = (xr[i] - mu) * rs * w[i] + b[i];
    }
}

// ---------------- final LN + head matvec ----------------
__global__ __launch_bounds__(256) void head_kernel(
    const float* __restrict__ x, const float* __restrict__ lw,
    const float* __restrict__ lb, const float* __restrict__ wh,
    float* __restrict__ out)
{
    int row = blockIdx.x;
    const float* xr = x + (size_t)row * CDIM;
    float s = 0.f, s2 = 0.f;
    for (int i = threadIdx.x; i < CDIM; i += 256) {
        float v = xr[i]; s += v; s2 += v * v;
    }
    #pragma unroll
    for (int o = 16; o; o >>= 1) {
        s  += __shfl_xor_sync(0xffffffffu, s,  o);
        s2 += __shfl_xor_sync(0xffffffffu, s2, o);
    }
    __shared__ float rbuf[16];
    int wid = threadIdx.x >> 5, lane = threadIdx.x & 31;
    if (lane == 0) { rbuf[wid] = s; rbuf[8 + wid] = s2; }
    __syncthreads();
    float ts = 0.f, ts2 = 0.f;
    #pragma unroll
    for (int i = 0; i < 8; i++) { ts += rbuf[i]; ts2 += rbuf[8 + i]; }
    float mu  = ts * (1.0f / CDIM);
    float var = ts2 * (1.0f / CDIM) - mu * mu;
    float rs  = rsqrtf(var + 1e-5f);

    float acc = 0.f;
    for (int i = threadIdx.x; i < CDIM; i += 256) {
        float hn = (xr[i] - mu) * rs * lw[i] + lb[i];
        acc += hn * wh[i];
    }
    #pragma unroll
    for (int o = 16; o; o >>= 1) acc += __shfl_xor_sync(0xffffffffu, acc, o);
    __syncthreads();
    if (lane == 0) rbuf[wid] = acc;
    __syncthreads();
    if (threadIdx.x == 0) {
        float t = 0.f;
        #pragma unroll
        for (int i = 0; i < 8; i++) t += rbuf[i];
        out[row] = t;
    }
}

// ======================= TF32 tensor-core GEMM =======================
// C[M,N] = A[M,K] @ B[K,N] (+bias / +residual / gelu)
// Block tile 128x128x32, 256 threads (8 warps, 2x4), warp tile 64x32.
// mma.sync.m16n8k8 tf32, cp.async 2-stage pipeline.

#define BM 128
#define BN 128
#define BK 32
#define AS_STRIDE 36              // conflict-free A frag loads (4m+k distinct)
#define BS_STRIDE 136             // conflict-free B frag loads (8k+n distinct)
#define A_SZ (BM * AS_STRIDE)     // 4608 floats
#define B_SZ (BK * BS_STRIDE)     // 4352 floats
#define STAGE_SZ (A_SZ + B_SZ)    // 8960 floats
#define GEMM_SMEM (2 * STAGE_SZ * 4)  // 71680 bytes

__device__ __forceinline__ float gelu_tanh(float v) {
    float c = 0.7978845608028654f * (v + 0.044715f * v * v * v);
    return 0.5f * v * (1.0f + tanhf(c));
}

__device__ __forceinline__ unsigned f2tf32(float x) {
    unsigned r;
    asm("cvt.rna.tf32.f32 %0, %1;" : "=r"(r) : "f"(x));
    return r;
}

__device__ __forceinline__ void cp_async16(float* smem_dst, const float* gmem_src) {
    unsigned s = (unsigned)__cvta_generic_to_shared(smem_dst);
    asm volatile("cp.async.cg.shared.global [%0], [%1], 16;\n" :: "r"(s), "l"(gmem_src));
}

#define MMA_TF32(d, a, b) \
    asm volatile( \
        "mma.sync.aligned.m16n8k8.row.col.f32.tf32.tf32.f32 " \
        "{%0,%1,%2,%3},{%4,%5,%6,%7},{%8,%9},{%0,%1,%2,%3};" \
        : "+f"(d[0]), "+f"(d[1]), "+f"(d[2]), "+f"(d[3]) \
        : "r"(a[0]), "r"(a[1]), "r"(a[2]), "r"(a[3]), "r"(b[0]), "r"(b[1]))

template <int EPI>  // 0=+bias  1=+bias+residual  2=+bias,gelu
__global__ __launch_bounds__(256, 2) void tgemm_kernel(
    const float* __restrict__ A, const float* __restrict__ B,
    const float* __restrict__ bias, const float* __restrict__ R,
    float* __restrict__ C, int M, int N, int K)
{
    extern __shared__ float sm[];
    int tid = threadIdx.x;
    int bm = blockIdx.y, bn = blockIdx.x;
    int lane = tid & 31, wid = tid >> 5;
    int wm = wid >> 2;            // 0..1
    int wn = wid & 3;             // 0..3
    int r0 = lane >> 2;           // groupID 0..7
    int c0 = lane & 3;            // 0..3

    const float* Ag = A + (size_t)(bm * BM) * K;
    const float* Bg = B + bn * BN;

    float acc[4][4][4];
    #pragma unroll
    for (int i = 0; i < 4; i++)
        #pragma unroll
        for (int j = 0; j < 4; j++)
            #pragma unroll
            for (int q = 0; q < 4; q++) acc[i][j][q] = 0.f;

    const int niter = K / BK;

    // tile loader: stage buf, k offset
    #define LOAD_TILE(buf, k0)                                                   \
    {                                                                            \
        float* As_ = sm + (buf) * STAGE_SZ;                                      \
        float* Bs_ = As_ + A_SZ;                                                 \
        _Pragma("unroll")                                                        \
        for (int p = 0; p < 4; p++) {                                            \
            int j = tid + p * 256;                                               \
            int ar = j >> 3, ak = (j & 7) * 4;                                   \
            cp_async16(&As_[ar * AS_STRIDE + ak],                                \
                       Ag + (size_t)ar * K + (k0) + ak);                         \
            int br = j >> 5, bn4 = (j & 31) * 4;                                 \
            cp_async16(&Bs_[br * BS_STRIDE + bn4],                               \
                       Bg + (size_t)((k0) + br) * N + bn4);                      \
        }                                                                        \
    }

    LOAD_TILE(0, 0);
    asm volatile("cp.async.commit_group;\n" ::);

    for (int it = 0; it < niter; it++) {
        if (it + 1 < niter) LOAD_TILE((it + 1) & 1, (it + 1) * BK);
        asm volatile("cp.async.commit_group;\n" ::);
        asm volatile("cp.async.wait_group 1;\n" ::);
        __syncthreads();

        const float* As = sm + (it & 1) * STAGE_SZ;
        const float* Bs = As + A_SZ;

        #pragma unroll
        for (int ks = 0; ks < 4; ks++) {
            unsigned a[4][4], b[4][2];
            #pragma unroll
            for (int mt = 0; mt < 4; mt++) {
                int m0 = wm * 64 + mt * 16 + r0;
                int kk = ks * 8 + c0;
                a[mt][0] = f2tf32(As[m0 * AS_STRIDE + kk]);
                a[mt][1] = f2tf32(As[(m0 + 8) * AS_STRIDE + kk]);
                a[mt][2] = f2tf32(As[m0 * AS_STRIDE + kk + 4]);
                a[mt][3] = f2tf32(As[(m0 + 8) * AS_STRIDE + kk + 4]);
            }
            #pragma unroll
            for (int nt = 0; nt < 4; nt++) {
                int n0 = wn * 32 + nt * 8 + r0;
                int kk = ks * 8 + c0;
                b[nt][0] = f2tf32(Bs[kk * BS_STRIDE + n0]);
                b[nt][1] = f2tf32(Bs[(kk + 4) * BS_STRIDE + n0]);
            }
            #pragma unroll
            for (int mt = 0; mt < 4; mt++)
                #pragma unroll
                for (int nt = 0; nt < 4; nt++)
                    MMA_TF32(acc[mt][nt], a[mt], b[nt]);
        }
        __syncthreads();
    }

    // ---------------- epilogue ----------------
    #pragma unroll
    for (int mt = 0; mt < 4; mt++) {
        int row0 = bm * BM + wm * 64 + mt * 16 + r0;
        #pragma unroll
        for (int nt = 0; nt < 4; nt++) {
            int col = bn * BN + wn * 32 + nt * 8 + c0 * 2;
            float b0 = bias[col], b1 = bias[col + 1];
            float v00 = acc[mt][nt][0] + b0;
            float v01 = acc[mt][nt][1] + b1;
            float v10 = acc[mt][nt][2] + b0;
            float v11 = acc[mt][nt][3] + b1;
            if (EPI == 1) {
                const float* r0p = R + (size_t)row0 * N + col;
                const float* r1p = R + (size_t)(row0 + 8) * N + col;
                v00 += r0p[0]; v01 += r0p[1];
                v10 += r1p[0]; v11 += r1p[1];
            } else if (EPI == 2) {
                v00 = gelu_tanh(v00); v01 = gelu_tanh(v01);
                v10 = gelu_tanh(v10); v11 = gelu_tanh(v11);
            }
            float2 o0 = make_float2(v00, v01);
            float2 o1 = make_float2(v10, v11);
            *(float2*)(C + (size_t)row0 * N + col) = o0;
            *(float2*)(C + (size_t)(row0 + 8) * N + col) = o1;
        }
    }
}

// ---------------- flash attention (fp32, causal) ----------------
__global__ __launch_bounds__(256) void attn_kernel(
    const float* __restrict__ qkv, float* __restrict__ y)
{
    extern __shared__ float sm[];
    float* Qs  = sm;                 // [64][65]
    float* Kts = Qs  + 64 * 65;      // [64 d][68]
    float* Vs  = Kts + 64 * 68;      // [64 kc][68]
    float* Ss  = Vs  + 64 * 68;      // [64 qr][68]

    int tid = threadIdx.x;
    int qt = blockIdx.x;
    int bh = blockIdx.y;
    int b = bh / HEADS, h = bh - (bh / HEADS) * HEADS;

    size_t rowbase = (size_t)b * TSEQ;
    int qoff = h * DHEAD;
    int koff = CDIM + h * DHEAD;
    int voff = 2 * CDIM + h * DHEAD;

    int lc  = (tid & 15) * 4;
    int lr0 = tid >> 4;

    #pragma unroll
    for (int rr = lr0; rr < 64; rr += 16) {
        float4 v = *(const float4*)(qkv + (rowbase + qt * 64 + rr) * C3 + qoff + lc);
        Qs[rr * 65 + lc + 0] = v.x;
        Qs[rr * 65 + lc + 1] = v.y;
        Qs[rr * 65 + lc + 2] = v.z;
        Qs[rr * 65 + lc + 3] = v.w;
    }

    int qr  = tid >> 2;
    int seg = tid & 3;
    int qg  = qt * 64 + qr;

    float m_i = -1e30f, l_i = 0.f;
    float O[16];
    #pragma unroll
    for (int i = 0; i < 16; i++) O[i] = 0.f;

    const float scale = 0.125f;

    for (int kt = 0; kt <= qt; kt++) {
        #pragma unroll
        for (int rr = lr0; rr < 64; rr += 16) {
            const float* base = qkv + (rowbase + kt * 64 + rr) * C3;
            float4 kv = *(const float4*)(base + koff + lc);
            Kts[(lc + 0) * 68 + rr] = kv.x;
            Kts[(lc + 1) * 68 + rr] = kv.y;
            Kts[(lc + 2) * 68 + rr] = kv.z;
            Kts[(lc + 3) * 68 + rr] = kv.w;
            float4 vv = *(const float4*)(base + voff + lc);
            Vs[rr * 68 + lc + 0] = vv.x;
            Vs[rr * 68 + lc + 1] = vv.y;
            Vs[rr * 68 + lc + 2] = vv.z;
            Vs[rr * 68 + lc + 3] = vv.w;
        }
        __syncthreads();

        float sacc[16];
        #pragma unroll
        for (int j = 0; j < 16; j++) sacc[j] = 0.f;
        const float* KtsBase = Kts + seg * 16;
        const float* Qrow = Qs + qr * 65;
        #pragma unroll 8
        for (int d = 0; d < 64; d++) {
            float qv = Qrow[d];
            float4 k0 = *(const float4*)(KtsBase + d * 68 + 0);
            float4 k1 = *(const float4*)(KtsBase + d * 68 + 4);
            float4 k2 = *(const float4*)(KtsBase + d * 68 + 8);
            float4 k3 = *(const float4*)(KtsBase + d * 68 + 12);
            sacc[0]  += qv * k0.x; sacc[1]  += qv * k0.y;
            sacc[2]  += qv * k0.z; sacc[3]  += qv * k0.w;
            sacc[4]  += qv * k1.x; sacc[5]  += qv * k1.y;
            sacc[6]  += qv * k1.z; sacc[7]  += qv * k1.w;
            sacc[8]  += qv * k2.x; sacc[9]  += qv * k2.y;
            sacc[10] += qv * k2.z; sacc[11] += qv * k2.w;
            sacc[12] += qv * k3.x; sacc[13] += qv * k3.y;
            sacc[14] += qv * k3.z; sacc[15] += qv * k3.w;
        }

        float mblk = -1e30f;
        #pragma unroll
        for (int j = 0; j < 16; j++) {
            int kg = kt * 64 + seg * 16 + j;
            float s = sacc[j] * scale;
            if (kg > qg) s = -1e30f;
            sacc[j] = s;
            mblk = fmaxf(mblk, s);
        }
        mblk = fmaxf(mblk, __shfl_xor_sync(0xffffffffu, mblk, 1));
        mblk = fmaxf(mblk, __shfl_xor_sync(0xffffffffu, mblk, 2));
        float m_new = fmaxf(m_i, mblk);
        float alpha = __expf(m_i - m_new);
        float lblk = 0.f;
        #pragma unroll
        for (int j = 0; j < 16; j++) {
            float p = __expf(sacc[j] - m_new);
            sacc[j] = p;
            lblk += p;
        }
        lblk += __shfl_xor_sync(0xffffffffu, lblk, 1);
        lblk += __shfl_xor_sync(0xffffffffu, lblk, 2);
        l_i = l_i * alpha + lblk;
        m_i = m_new;

        #pragma unroll
        for (int j = 0; j < 16; j++)
            Ss[qr * 68 + seg * 16 + j] = sacc[j];
        __syncthreads();

        #pragma unroll
        for (int i = 0; i < 16; i++) O[i] *= alpha;
        const float* VsBase = Vs + seg * 16;
        const float* Srow = Ss + qr * 68;
        #pragma unroll 4
        for (int j = 0; j < 64; j++) {
            float s = Srow[j];
            float4 v0 = *(const float4*)(VsBase + j * 68 + 0);
            float4 v1 = *(const float4*)(VsBase + j * 68 + 4);
            float4 v2 = *(const float4*)(VsBase + j * 68 + 8);
            float4 v3 = *(const float4*)(VsBase + j * 68 + 12);
            O[0]  += s * v0.x; O[1]  += s * v0.y; O[2]  += s * v0.z; O[3]  += s * v0.w;
            O[4]  += s * v1.x; O[5]  += s * v1.y; O[6]  += s * v1.z; O[7]  += s * v1.w;
            O[8]  += s * v2.x; O[9]  += s * v2.y; O[10] += s * v2.z; O[11] += s * v2.w;
            O[12] += s * v3.x; O[13] += s * v3.y; O[14] += s * v3.z; O[15] += s * v3.w;
        }
        __syncthreads();
    }

    float inv = 1.f / l_i;
    float* yrow = y + (rowbase + qt * 64 + qr) * CDIM + h * DHEAD + seg * 16;
    #pragma unroll
    for (int q4 = 0; q4 < 4; q4++) {
        float4 v;
        v.x = O[q4 * 4 + 0] * inv;
        v.y = O[q4 * 4 + 1] * inv;
        v.z = O[q4 * 4 + 2] * inv;
        v.w = O[q4 * 4 + 3] * inv;
        *(float4*)(yrow + q4 * 4) = v;
    }
}

// ---------------- launch ----------------
extern "C" void kernel_launch(void* const* d_in, const int* in_sizes, int n_in,
                              void* d_out, int out_size)
{
    const int*   idx    = (const int*)  d_in[0];
    const float* wte    = (const float*)d_in[1];
    const float* wpe    = (const float*)d_in[2];
    const float* ln1_w  = (const float*)d_in[3];
    const float* ln1_b  = (const float*)d_in[4];
    const float* w_qkv  = (const float*)d_in[5];
    const float* b_qkv  = (const float*)d_in[6];
    const float* w_ao   = (const float*)d_in[7];
    const float* b_ao   = (const float*)d_in[8];
    const float* ln2_w  = (const float*)d_in[9];
    const float* ln2_b  = (const float*)d_in[10];
    const float* w_fc   = (const float*)d_in[11];
    const float* b_fc   = (const float*)d_in[12];
    const float* w_fp   = (const float*)d_in[13];
    const float* b_fp   = (const float*)d_in[14];
    const float* lnf_w  = (const float*)d_in[15];
    const float* lnf_b  = (const float*)d_in[16];
    const float* w_head = (const float*)d_in[17];
    float* out = (float*)d_out;

    float *x, *h, *qkvb, *yb, *fcb;
    cudaGetSymbolAddress((void**)&x,    g_x);
    cudaGetSymbolAddress((void**)&h,    g_h);
    cudaGetSymbolAddress((void**)&qkvb, g_qkv);
    cudaGetSymbolAddress((void**)&yb,   g_y);
    cudaGetSymbolAddress((void**)&fcb,  g_fc);

    const int attn_smem = (64 * 65 + 64 * 68 + 64 * 68 + 64 * 68) * sizeof(float);
    static bool attrs_set = false;
    cudaFuncSetAttribute(attn_kernel, cudaFuncAttributeMaxDynamicSharedMemorySize, attn_smem);
    cudaFuncSetAttribute(tgemm_kernel<0>, cudaFuncAttributeMaxDynamicSharedMemorySize, GEMM_SMEM);
    cudaFuncSetAttribute(tgemm_kernel<1>, cudaFuncAttributeMaxDynamicSharedMemorySize, GEMM_SMEM);
    cudaFuncSetAttribute(tgemm_kernel<2>, cudaFuncAttributeMaxDynamicSharedMemorySize, GEMM_SMEM);
    (void)attrs_set;

    embed_kernel<<<(MROWS * CDIM) / 256, 256>>>(idx, wte, wpe, x);

    for (int l = 0; l < LAYERS; l++) {
        ln_kernel<<<MROWS, 256>>>(x, ln1_w + l * CDIM, ln1_b + l * CDIM, h);
        tgemm_kernel<0><<<dim3(C3 / BN, MROWS / BM), 256, GEMM_SMEM>>>(
            h, w_qkv + (size_t)l * CDIM * C3, b_qkv + l * C3, nullptr, qkvb,
            MROWS, C3, CDIM);
        attn_kernel<<<dim3(TSEQ / 64, BATCH * HEADS), 256, attn_smem>>>(qkvb, yb);
        tgemm_kernel<1><<<dim3(CDIM / BN, MROWS / BM), 256, GEMM_SMEM>>>(
            yb, w_ao + (size_t)l * CDIM * CDIM, b_ao + l * CDIM, x, x,
            MROWS, CDIM, CDIM);
        ln_kernel<<<MROWS, 256>>>(x, ln2_w + l * CDIM, ln2_b + l * CDIM, h);
        tgemm_kernel<2><<<dim3(C4 / BN, MROWS / BM), 256, GEMM_SMEM>>>(
            h, w_fc + (size_t)l * CDIM * C4, b_fc + l * C4, nullptr, fcb,
            MROWS, C4, CDIM);
        tgemm_kernel<1><<<dim3(CDIM / BN, MROWS / BM), 256, GEMM_SMEM>>>(
            fcb, w_fp + (size_t)l * C4 * CDIM, b_fp + l * CDIM, x, x,
            MROWS, CDIM, C4);
    }

    head_kernel<<<MROWS, 256>>>(x, lnf_w, lnf_b, w_head, out);
}

// round 4
// speedup vs baseline: 1.9860x; 1.1937x over previous
#include <cuda_runtime.h>
#include <cuda_fp16.h>
#include <math.h>
#include <stdint.h>

// ---------------- problem constants ----------------
#define LAYERS 12
#define HEADS  12
#define CDIM   768
#define TSEQ   1024
#define BATCH  4
#define MROWS  (BATCH*TSEQ)      // 4096
#define C3     (3*CDIM)          // 2304
#define C4     (4*CDIM)          // 3072
#define DHEAD  64

// ---------------- scratch (device globals: no allocation allowed) ----------
__device__ float  g_x  [MROWS*CDIM];          // fp32 residual stream
__device__ float  g_qkv[MROWS*C3];            // fp32 qkv (attention input)
__device__ __half g_h  [MROWS*CDIM];          // fp16 LN output (GEMM A)
__device__ __half g_y  [MROWS*CDIM];          // fp16 attention output
__device__ __half g_fc [MROWS*C4];            // fp16 gelu output
// transposed (to [N,K] K-major) fp16 weights
__device__ __half g_wqkvT[LAYERS*C3*CDIM];
__device__ __half g_waoT [LAYERS*CDIM*CDIM];
__device__ __half g_wfcT [LAYERS*C4*CDIM];
__device__ __half g_wfpT [LAYERS*CDIM*C4];

// ---------------- helpers ----------------
__device__ __forceinline__ uint32_t smem_u32(const void* p) {
    uint32_t a;
    asm("{ .reg .u64 t; cvta.to.shared.u64 t, %1; cvt.u32.u64 %0, t; }"
        : "=r"(a) : "l"(p));
    return a;
}
__device__ __forceinline__ void cpa16(uint32_t saddr, const void* g) {
    asm volatile("cp.async.cg.shared.global [%0], [%1], 16;" :: "r"(saddr), "l"(g));
}
#define CP_COMMIT()  asm volatile("cp.async.commit_group;" ::: "memory")
#define CP_WAIT(n)   asm volatile("cp.async.wait_group %0;" :: "n"(n) : "memory")

#define LDMATRIX_X4(r0, r1, r2, r3, addr) \
    asm volatile("ldmatrix.sync.aligned.m8n8.x4.shared.b16 {%0,%1,%2,%3}, [%4];" \
        : "=r"(r0), "=r"(r1), "=r"(r2), "=r"(r3) : "r"(addr))

#define MMA_F16(d, a, b) \
    asm volatile( \
        "mma.sync.aligned.m16n8k16.row.col.f32.f16.f16.f32 " \
        "{%0,%1,%2,%3},{%4,%5,%6,%7},{%8,%9},{%0,%1,%2,%3};" \
        : "+f"((d)[0]), "+f"((d)[1]), "+f"((d)[2]), "+f"((d)[3]) \
        : "r"((a)[0]), "r"((a)[1]), "r"((a)[2]), "r"((a)[3]), \
          "r"((b)[0]), "r"((b)[1]))

__device__ __forceinline__ float gelu_tanh(float v) {
    float c = 0.7978845608028654f * (v + 0.044715f * v * v * v);
    return 0.5f * v * (1.0f + tanhf(c));
}

// ---------------- embedding ----------------
__global__ __launch_bounds__(256) void embed_kernel(
    const int* __restrict__ idx, const float* __restrict__ wte,
    const float* __restrict__ wpe, float* __restrict__ x)
{
    int i = blockIdx.x * 256 + threadIdx.x;
    int row = i / CDIM;
    int c   = i - row * CDIM;
    int t   = row & (TSEQ - 1);
    int id  = idx[row];
    x[i] = wte[(size_t)id * CDIM + c] + wpe[(size_t)t * CDIM + c];
}

// ---------------- weight transpose (fp32 [K,N] -> fp16 [N,K]) --------------
__global__ __launch_bounds__(256) void transpose_kernel(
    const float* __restrict__ W, __half* __restrict__ WT, int K, int N)
{
    __shared__ float t[32][33];
    int l = blockIdx.z;
    const float* Wl = W + (size_t)l * K * N;
    __half* WTl = WT + (size_t)l * N * K;
    int k0 = blockIdx.y * 32, n0 = blockIdx.x * 32;
    int tx = threadIdx.x & 31, ty = threadIdx.x >> 5;   // 32 x 8
    #pragma unroll
    for (int r = ty; r < 32; r += 8)
        t[r][tx] = Wl[(size_t)(k0 + r) * N + n0 + tx];
    __syncthreads();
    #pragma unroll
    for (int r = ty; r < 32; r += 8)
        WTl[(size_t)(n0 + r) * K + k0 + tx] = __float2half_rn(t[tx][r]);
}

// ---------------- layernorm (fp16 output) ----------------
__global__ __launch_bounds__(256) void ln_kernel(
    const float* __restrict__ x, const float* __restrict__ w,
    const float* __restrict__ b, __half* __restrict__ out)
{
    int row = blockIdx.x;
    const float* xr = x + (size_t)row * CDIM;
    float s = 0.f, s2 = 0.f;
    for (int i = threadIdx.x; i < CDIM; i += 256) {
        float v = xr[i]; s += v; s2 += v * v;
    }
    #pragma unroll
    for (int o = 16; o; o >>= 1) {
        s  += __shfl_xor_sync(0xffffffffu, s,  o);
        s2 += __shfl_xor_sync(0xffffffffu, s2, o);
    }
    __shared__ float rbuf[16];
    int wid = threadIdx.x >> 5, lane = threadIdx.x & 31;
    if (lane == 0) { rbuf[wid] = s; rbuf[8 + wid] = s2; }
    __syncthreads();
    float ts = 0.f, ts2 = 0.f;
    #pragma unroll
    for (int i = 0; i < 8; i++) { ts += rbuf[i]; ts2 += rbuf[8 + i]; }
    float mu  = ts * (1.0f / CDIM);
    float var = ts2 * (1.0f / CDIM) - mu * mu;
    float rs  = rsqrtf(var + 1e-5f);
    __half* orow = out + (size_t)row * CDIM;
    for (int i = threadIdx.x; i < CDIM; i += 256) {
        orow[i] = __float2half_rn((xr[i] - mu) * rs * w[i] + b[i]);
    }
}

// ---------------- final LN + head matvec ----------------
__global__ __launch_bounds__(256) void head_kernel(
    const float* __restrict__ x, const float* __restrict__ lw,
    const float* __restrict__ lb, const float* __restrict__ wh,
    float* __restrict__ out)
{
    int row = blockIdx.x;
    const float* xr = x + (size_t)row * CDIM;
    float s = 0.f, s2 = 0.f;
    for (int i = threadIdx.x; i < CDIM; i += 256) {
        float v = xr[i]; s += v; s2 += v * v;
    }
    #pragma unroll
    for (int o = 16; o; o >>= 1) {
        s  += __shfl_xor_sync(0xffffffffu, s,  o);
        s2 += __shfl_xor_sync(0xffffffffu, s2, o);
    }
    __shared__ float rbuf[16];
    int wid = threadIdx.x >> 5, lane = threadIdx.x & 31;
    if (lane == 0) { rbuf[wid] = s; rbuf[8 + wid] = s2; }
    __syncthreads();
    float ts = 0.f, ts2 = 0.f;
    #pragma unroll
    for (int i = 0; i < 8; i++) { ts += rbuf[i]; ts2 += rbuf[8 + i]; }
    float mu  = ts * (1.0f / CDIM);
    float var = ts2 * (1.0f / CDIM) - mu * mu;
    float rs  = rsqrtf(var + 1e-5f);

    float acc = 0.f;
    for (int i = threadIdx.x; i < CDIM; i += 256) {
        float hn = (xr[i] - mu) * rs * lw[i] + lb[i];
        acc += hn * wh[i];
    }
    #pragma unroll
    for (int o = 16; o; o >>= 1) acc += __shfl_xor_sync(0xffffffffu, acc, o);
    __syncthreads();
    if (lane == 0) rbuf[wid] = acc;
    __syncthreads();
    if (threadIdx.x == 0) {
        float t = 0.f;
        #pragma unroll
        for (int i = 0; i < 8; i++) t += rbuf[i];
        out[row] = t;
    }
}

// ======================= fp16 tensor-core GEMM (mma.sync) ====================
// C[M,N] = A[M,K] @ BT[N,K]^T.  A, BT fp16 K-major; C fp32 (or fp16 for EPI 2).
// Block 128x128, BK=32, 8 warps (2x4), warp tile 64x32, 4-stage cp.async.
// smem tile: 128 rows x 64 bytes (32 halves); swizzle chunk16 ^= (row>>1)&3.
#define NSTAGE 4
#define STAGE_BYTES 16384             // A 8KB + B 8KB
#define HG_SMEM (NSTAGE*STAGE_BYTES)  // 65536

template <int EPI>  // 0=+bias->f32  1=+bias+residual->f32  2=+bias,gelu->f16
__global__ __launch_bounds__(256, 2) void hgemm(
    const __half* __restrict__ A, const __half* __restrict__ BT,
    const float* __restrict__ bias, const float* __restrict__ R,
    void* __restrict__ Cv, int M, int N, int K)
{
    extern __shared__ __align__(128) char smem[];
    uint32_t sbase = smem_u32(smem);
    int tid = threadIdx.x, lane = tid & 31, wid = tid >> 5;
    int wm = wid >> 2, wn = wid & 3;
    int bm = blockIdx.y, bn = blockIdx.x;
    const __half* Ag = A  + (size_t)bm * 128 * K;
    const __half* Bg = BT + (size_t)bn * 128 * K;
    const int nch = K >> 5;

    float acc[4][4][4];
    #pragma unroll
    for (int i = 0; i < 4; i++)
        #pragma unroll
        for (int j = 0; j < 4; j++)
            #pragma unroll
            for (int q = 0; q < 4; q++) acc[i][j][q] = 0.f;

    // loader: 512 A-chunks + 512 B-chunks of 16B; each thread does 2+2
    #define LOADC(c, s)                                                        \
    {                                                                          \
        uint32_t st_ = sbase + (s) * STAGE_BYTES;                              \
        int k0_ = (c) * 32;                                                    \
        _Pragma("unroll")                                                      \
        for (int p = 0; p < 2; p++) {                                          \
            int j = tid + p * 256;                                             \
            int row = j >> 2, ch = j & 3;                                      \
            uint32_t off = row * 64 + 16 * (ch ^ ((row >> 1) & 3));            \
            cpa16(st_ + off, Ag + (size_t)row * K + k0_ + ch * 8);             \
            cpa16(st_ + 8192 + off, Bg + (size_t)row * K + k0_ + ch * 8);      \
        }                                                                      \
        CP_COMMIT();                                                           \
    }

    LOADC(0, 0); LOADC(1, 1); LOADC(2, 2);

    // ldmatrix lane->row/chunk mappings
    int rA = lane & 15;            // row within 16-row A tile
    int hA = lane >> 4;            // 0 = k-lo chunk, 1 = k-hi
    int rB = ((lane >> 4) << 3) + (lane & 7);   // row within 16-row B pair
    int hB = (lane >> 3) & 1;

    for (int c = 0; c < nch; c++) {
        if (c + 3 < nch) { LOADC(c + 3, (c + 3) & 3); } else { CP_COMMIT(); }
        CP_WAIT(3);
        __syncthreads();

        uint32_t abase = sbase + (c & 3) * STAGE_BYTES;
        uint32_t bbase = abase + 8192;

        #pragma unroll
        for (int ks = 0; ks < 2; ks++) {
            uint32_t afr[4][4];
            #pragma unroll
            for (int mt = 0; mt < 4; mt++) {
                int row = wm * 64 + mt * 16 + rA;
                uint32_t ad = abase + row * 64 +
                              16 * ((ks * 2 + hA) ^ ((row >> 1) & 3));
                LDMATRIX_X4(afr[mt][0], afr[mt][1], afr[mt][2], afr[mt][3], ad);
            }
            uint32_t bfr[4][2];
            #pragma unroll
            for (int pr = 0; pr < 2; pr++) {
                int row = wn * 32 + pr * 16 + rB;
                uint32_t bd = bbase + row * 64 +
                              16 * ((ks * 2 + hB) ^ ((row >> 1) & 3));
                uint32_t r0, r1, r2, r3;
                LDMATRIX_X4(r0, r1, r2, r3, bd);
                bfr[pr * 2][0] = r0; bfr[pr * 2][1] = r1;
                bfr[pr * 2 + 1][0] = r2; bfr[pr * 2 + 1][1] = r3;
            }
            #pragma unroll
            for (int mt = 0; mt < 4; mt++)
                #pragma unroll
                for (int nt = 0; nt < 4; nt++)
                    MMA_F16(acc[mt][nt], afr[mt], bfr[nt]);
        }
        __syncthreads();
    }

    // ---------------- epilogue ----------------
    int r0 = lane >> 2, c0 = lane & 3;
    #pragma unroll
    for (int mt = 0; mt < 4; mt++) {
        int row0 = bm * 128 + wm * 64 + mt * 16 + r0;
        #pragma unroll
        for (int nt = 0; nt < 4; nt++) {
            int col = bn * 128 + wn * 32 + nt * 8 + c0 * 2;
            float b0 = bias[col], b1 = bias[col + 1];
            float v00 = acc[mt][nt][0] + b0;
            float v01 = acc[mt][nt][1] + b1;
            float v10 = acc[mt][nt][2] + b0;
            float v11 = acc[mt][nt][3] + b1;
            if (EPI == 1) {
                float* C = (float*)Cv;
                const float* r0p = R + (size_t)row0 * N + col;
                const float* r1p = R + (size_t)(row0 + 8) * N + col;
                v00 += r0p[0]; v01 += r0p[1];
                v10 += r1p[0]; v11 += r1p[1];
                *(float2*)(C + (size_t)row0 * N + col) = make_float2(v00, v01);
                *(float2*)(C + (size_t)(row0 + 8) * N + col) = make_float2(v10, v11);
            } else if (EPI == 2) {
                __half* C = (__half*)Cv;
                __half2 o0 = __floats2half2_rn(gelu_tanh(v00), gelu_tanh(v01));
                __half2 o1 = __floats2half2_rn(gelu_tanh(v10), gelu_tanh(v11));
                *(__half2*)(C + (size_t)row0 * N + col) = o0;
                *(__half2*)(C + (size_t)(row0 + 8) * N + col) = o1;
            } else {
                float* C = (float*)Cv;
                *(float2*)(C + (size_t)row0 * N + col) = make_float2(v00, v01);
                *(float2*)(C + (size_t)(row0 + 8) * N + col) = make_float2(v10, v11);
            }
        }
    }
    #undef LOADC
}

// ---------------- flash attention (fp32 compute, fp16 output) ---------------
__global__ __launch_bounds__(256) void attn_kernel(
    const float* __restrict__ qkv, __half* __restrict__ y)
{
    extern __shared__ float sm[];
    float* Qs  = sm;                 // [64][65]
    float* Kts = Qs  + 64 * 65;      // [64 d][68]
    float* Vs  = Kts + 64 * 68;      // [64 kc][68]
    float* Ss  = Vs  + 64 * 68;      // [64 qr][68]

    int tid = threadIdx.x;
    int qt = blockIdx.x;
    int bh = blockIdx.y;
    int b = bh / HEADS, h = bh - (bh / HEADS) * HEADS;

    size_t rowbase = (size_t)b * TSEQ;
    int qoff = h * DHEAD;
    int koff = CDIM + h * DHEAD;
    int voff = 2 * CDIM + h * DHEAD;

    int lc  = (tid & 15) * 4;
    int lr0 = tid >> 4;

    #pragma unroll
    for (int rr = lr0; rr < 64; rr += 16) {
        float4 v = *(const float4*)(qkv + (rowbase + qt * 64 + rr) * C3 + qoff + lc);
        Qs[rr * 65 + lc + 0] = v.x;
        Qs[rr * 65 + lc + 1] = v.y;
        Qs[rr * 65 + lc + 2] = v.z;
        Qs[rr * 65 + lc + 3] = v.w;
    }

    int qr  = tid >> 2;
    int seg = tid & 3;
    int qg  = qt * 64 + qr;

    float m_i = -1e30f, l_i = 0.f;
    float O[16];
    #pragma unroll
    for (int i = 0; i < 16; i++) O[i] = 0.f;

    const float scale = 0.125f;

    for (int kt = 0; kt <= qt; kt++) {
        #pragma unroll
        for (int rr = lr0; rr < 64; rr += 16) {
            const float* base = qkv + (rowbase + kt * 64 + rr) * C3;
            float4 kv = *(const float4*)(base + koff + lc);
            Kts[(lc + 0) * 68 + rr] = kv.x;
            Kts[(lc + 1) * 68 + rr] = kv.y;
            Kts[(lc + 2) * 68 + rr] = kv.z;
            Kts[(lc + 3) * 68 + rr] = kv.w;
            float4 vv = *(const float4*)(base + voff + lc);
            Vs[rr * 68 + lc + 0] = vv.x;
            Vs[rr * 68 + lc + 1] = vv.y;
            Vs[rr * 68 + lc + 2] = vv.z;
            Vs[rr * 68 + lc + 3] = vv.w;
        }
        __syncthreads();

        float sacc[16];
        #pragma unroll
        for (int j = 0; j < 16; j++) sacc[j] = 0.f;
        const float* KtsBase = Kts + seg * 16;
        const float* Qrow = Qs + qr * 65;
        #pragma unroll 8
        for (int d = 0; d < 64; d++) {
            float qv = Qrow[d];
            float4 k0 = *(const float4*)(KtsBase + d * 68 + 0);
            float4 k1 = *(const float4*)(KtsBase + d * 68 + 4);
            float4 k2 = *(const float4*)(KtsBase + d * 68 + 8);
            float4 k3 = *(const float4*)(KtsBase + d * 68 + 12);
            sacc[0]  += qv * k0.x; sacc[1]  += qv * k0.y;
            sacc[2]  += qv * k0.z; sacc[3]  += qv * k0.w;
            sacc[4]  += qv * k1.x; sacc[5]  += qv * k1.y;
            sacc[6]  += qv * k1.z; sacc[7]  += qv * k1.w;
            sacc[8]  += qv * k2.x; sacc[9]  += qv * k2.y;
            sacc[10] += qv * k2.z; sacc[11] += qv * k2.w;
            sacc[12] += qv * k3.x; sacc[13] += qv * k3.y;
            sacc[14] += qv * k3.z; sacc[15] += qv * k3.w;
        }

        float mblk = -1e30f;
        #pragma unroll
        for (int j = 0; j < 16; j++) {
            int kg = kt * 64 + seg * 16 + j;
            float s = sacc[j] * scale;
            if (kg > qg) s = -1e30f;
            sacc[j] = s;
            mblk = fmaxf(mblk, s);
        }
        mblk = fmaxf(mblk, __shfl_xor_sync(0xffffffffu, mblk, 1));
        mblk = fmaxf(mblk, __shfl_xor_sync(0xffffffffu, mblk, 2));
        float m_new = fmaxf(m_i, mblk);
        float alpha = __expf(m_i - m_new);
        float lblk = 0.f;
        #pragma unroll
        for (int j = 0; j < 16; j++) {
            float p = __expf(sacc[j] - m_new);
            sacc[j] = p;
            lblk += p;
        }
        lblk += __shfl_xor_sync(0xffffffffu, lblk, 1);
        lblk += __shfl_xor_sync(0xffffffffu, lblk, 2);
        l_i = l_i * alpha + lblk;
        m_i = m_new;

        #pragma unroll
        for (int j = 0; j < 16; j++)
            Ss[qr * 68 + seg * 16 + j] = sacc[j];
        __syncthreads();

        #pragma unroll
        for (int i = 0; i < 16; i++) O[i] *= alpha;
        const float* VsBase = Vs + seg * 16;
        const float* Srow = Ss + qr * 68;
        #pragma unroll 4
        for (int j = 0; j < 64; j++) {
            float s = Srow[j];
            float4 v0 = *(const float4*)(VsBase + j * 68 + 0);
            float4 v1 = *(const float4*)(VsBase + j * 68 + 4);
            float4 v2 = *(const float4*)(VsBase + j * 68 + 8);
            float4 v3 = *(const float4*)(VsBase + j * 68 + 12);
            O[0]  += s * v0.x; O[1]  += s * v0.y; O[2]  += s * v0.z; O[3]  += s * v0.w;
            O[4]  += s * v1.x; O[5]  += s * v1.y; O[6]  += s * v1.z; O[7]  += s * v1.w;
            O[8]  += s * v2.x; O[9]  += s * v2.y; O[10] += s * v2.z; O[11] += s * v2.w;
            O[12] += s * v3.x; O[13] += s * v3.y; O[14] += s * v3.z; O[15] += s * v3.w;
        }
        __syncthreads();
    }

    float inv = 1.f / l_i;
    __half* yrow = y + (rowbase + qt * 64 + qr) * CDIM + h * DHEAD + seg * 16;
    __half2 pk[8];
    #pragma unroll
    for (int i = 0; i < 8; i++)
        pk[i] = __floats2half2_rn(O[2 * i] * inv, O[2 * i + 1] * inv);
    *(uint4*)(yrow)     = *(uint4*)&pk[0];
    *(uint4*)(yrow + 8) = *(uint4*)&pk[4];
}

// ---------------- launch ----------------
extern "C" void kernel_launch(void* const* d_in, const int* in_sizes, int n_in,
                              void* d_out, int out_size)
{
    const int*   idx    = (const int*)  d_in[0];
    const float* wte    = (const float*)d_in[1];
    const float* wpe    = (const float*)d_in[2];
    const float* ln1_w  = (const float*)d_in[3];
    const float* ln1_b  = (const float*)d_in[4];
    const float* w_qkv  = (const float*)d_in[5];
    const float* b_qkv  = (const float*)d_in[6];
    const float* w_ao   = (const float*)d_in[7];
    const float* b_ao   = (const float*)d_in[8];
    const float* ln2_w  = (const float*)d_in[9];
    const float* ln2_b  = (const float*)d_in[10];
    const float* w_fc   = (const float*)d_in[11];
    const float* b_fc   = (const float*)d_in[12];
    const float* w_fp   = (const float*)d_in[13];
    const float* b_fp   = (const float*)d_in[14];
    const float* lnf_w  = (const float*)d_in[15];
    const float* lnf_b  = (const float*)d_in[16];
    const float* w_head = (const float*)d_in[17];
    float* out = (float*)d_out;

    float *x, *qkvb;
    __half *hh, *yh, *fch, *wqkvT, *waoT, *wfcT, *wfpT;
    cudaGetSymbolAddress((void**)&x,    g_x);
    cudaGetSymbolAddress((void**)&qkvb, g_qkv);
    cudaGetSymbolAddress((void**)&hh,   g_h);
    cudaGetSymbolAddress((void**)&yh,   g_y);
    cudaGetSymbolAddress((void**)&fch,  g_fc);
    cudaGetSymbolAddress((void**)&wqkvT, g_wqkvT);
    cudaGetSymbolAddress((void**)&waoT,  g_waoT);
    cudaGetSymbolAddress((void**)&wfcT,  g_wfcT);
    cudaGetSymbolAddress((void**)&wfpT,  g_wfpT);

    const int attn_smem = (64 * 65 + 64 * 68 + 64 * 68 + 64 * 68) * sizeof(float);
    cudaFuncSetAttribute(attn_kernel, cudaFuncAttributeMaxDynamicSharedMemorySize, attn_smem);
    cudaFuncSetAttribute(hgemm<0>, cudaFuncAttributeMaxDynamicSharedMemorySize, HG_SMEM);
    cudaFuncSetAttribute(hgemm<1>, cudaFuncAttributeMaxDynamicSharedMemorySize, HG_SMEM);
    cudaFuncSetAttribute(hgemm<2>, cudaFuncAttributeMaxDynamicSharedMemorySize, HG_SMEM);

    // transpose + fp16-round all weights (once per call)
    transpose_kernel<<<dim3(C3 / 32, CDIM / 32, LAYERS), 256>>>(w_qkv, wqkvT, CDIM, C3);
    transpose_kernel<<<dim3(CDIM / 32, CDIM / 32, LAYERS), 256>>>(w_ao, waoT, CDIM, CDIM);
    transpose_kernel<<<dim3(C4 / 32, CDIM / 32, LAYERS), 256>>>(w_fc, wfcT, CDIM, C4);
    transpose_kernel<<<dim3(CDIM / 32, C4 / 32, LAYERS), 256>>>(w_fp, wfpT, C4, CDIM);

    embed_kernel<<<(MROWS * CDIM) / 256, 256>>>(idx, wte, wpe, x);

    for (int l = 0; l < LAYERS; l++) {
        ln_kernel<<<MROWS, 256>>>(x, ln1_w + l * CDIM, ln1_b + l * CDIM, hh);
        hgemm<0><<<dim3(C3 / 128, MROWS / 128), 256, HG_SMEM>>>(
            hh, wqkvT + (size_t)l * C3 * CDIM, b_qkv + l * C3, nullptr, qkvb,
            MROWS, C3, CDIM);
        attn_kernel<<<dim3(TSEQ / 64, BATCH * HEADS), 256, attn_smem>>>(qkvb, yh);
        hgemm<1><<<dim3(CDIM / 128, MROWS / 128), 256, HG_SMEM>>>(
            yh, waoT + (size_t)l * CDIM * CDIM, b_ao + l * CDIM, x, x,
            MROWS, CDIM, CDIM);
        ln_kernel<<<MROWS, 256>>>(x, ln2_w + l * CDIM, ln2_b + l * CDIM, hh);
        hgemm<2><<<dim3(C4 / 128, MROWS / 128), 256, HG_SMEM>>>(
            hh, wfcT + (size_t)l * C4 * CDIM, b_fc + l * C4, nullptr, fch,
            MROWS, C4, CDIM);
        hgemm<1><<<dim3(CDIM / 128, MROWS / 128), 256, HG_SMEM>>>(
            fch, wfpT + (size_t)l * CDIM * C4, b_fp + l * CDIM, x, x,
            MROWS, CDIM, C4);
    }

    head_kernel<<<MROWS, 256>>>(x, lnf_w, lnf_b, w_head, out);
}

// round 5
// speedup vs baseline: 2.0288x; 1.0216x over previous
#include <cuda_runtime.h>
#include <cuda_fp16.h>
#include <math.h>
#include <stdint.h>

// ---------------- problem constants ----------------
#define LAYERS 12
#define HEADS  12
#define CDIM   768
#define TSEQ   1024
#define BATCH  4
#define MROWS  (BATCH*TSEQ)      // 4096
#define C3     (3*CDIM)          // 2304
#define C4     (4*CDIM)          // 3072
#define DHEAD  64

// ---------------- scratch (device globals: no allocation allowed) ----------
__device__ float  g_x  [MROWS*CDIM];          // fp32 residual stream
__device__ float  g_qkv[MROWS*C3];            // fp32 qkv (attention input)
__device__ __half g_h  [MROWS*CDIM];          // fp16 LN output (GEMM A)
__device__ __half g_y  [MROWS*CDIM];          // fp16 attention output
__device__ __half g_fc [MROWS*C4];            // fp16 gelu output
// transposed (to [N,K] K-major) fp16 weights
__device__ __half g_wqkvT[LAYERS*C3*CDIM];
__device__ __half g_waoT [LAYERS*CDIM*CDIM];
__device__ __half g_wfcT [LAYERS*C4*CDIM];
__device__ __half g_wfpT [LAYERS*CDIM*C4];

// ---------------- helpers ----------------
__device__ __forceinline__ uint32_t smem_u32(const void* p) {
    uint32_t a;
    asm("{ .reg .u64 t; cvta.to.shared.u64 t, %1; cvt.u32.u64 %0, t; }"
        : "=r"(a) : "l"(p));
    return a;
}
__device__ __forceinline__ void cpa16(uint32_t saddr, const void* g) {
    asm volatile("cp.async.cg.shared.global [%0], [%1], 16;" :: "r"(saddr), "l"(g));
}
#define CP_COMMIT()  asm volatile("cp.async.commit_group;" ::: "memory")
#define CP_WAIT(n)   asm volatile("cp.async.wait_group %0;" :: "n"(n) : "memory")

#define LDMATRIX_X4(r0, r1, r2, r3, addr) \
    asm volatile("ldmatrix.sync.aligned.m8n8.x4.shared.b16 {%0,%1,%2,%3}, [%4];" \
        : "=r"(r0), "=r"(r1), "=r"(r2), "=r"(r3) : "r"(addr))

#define MMA_F16(d, a, b) \
    asm volatile( \
        "mma.sync.aligned.m16n8k16.row.col.f32.f16.f16.f32 " \
        "{%0,%1,%2,%3},{%4,%5,%6,%7},{%8,%9},{%0,%1,%2,%3};" \
        : "+f"((d)[0]), "+f"((d)[1]), "+f"((d)[2]), "+f"((d)[3]) \
        : "r"((a)[0]), "r"((a)[1]), "r"((a)[2]), "r"((a)[3]), \
          "r"((b)[0]), "r"((b)[1]))

__device__ __forceinline__ float gelu_tanh(float v) {
    float c = 0.7978845608028654f * (v + 0.044715f * v * v * v);
    return 0.5f * v * (1.0f + tanhf(c));
}

// ---------------- embedding ----------------
__global__ __launch_bounds__(256) void embed_kernel(
    const int* __restrict__ idx, const float* __restrict__ wte,
    const float* __restrict__ wpe, float* __restrict__ x)
{
    int i = blockIdx.x * 256 + threadIdx.x;
    int row = i / CDIM;
    int c   = i - row * CDIM;
    int t   = row & (TSEQ - 1);
    int id  = idx[row];
    x[i] = wte[(size_t)id * CDIM + c] + wpe[(size_t)t * CDIM + c];
}

// ---------------- weight transpose (fp32 [K,N] -> fp16 [N,K]) --------------
__global__ __launch_bounds__(256) void transpose_kernel(
    const float* __restrict__ W, __half* __restrict__ WT, int K, int N)
{
    __shared__ float t[32][33];
    int l = blockIdx.z;
    const float* Wl = W + (size_t)l * K * N;
    __half* WTl = WT + (size_t)l * N * K;
    int k0 = blockIdx.y * 32, n0 = blockIdx.x * 32;
    int tx = threadIdx.x & 31, ty = threadIdx.x >> 5;   // 32 x 8
    #pragma unroll
    for (int r = ty; r < 32; r += 8)
        t[r][tx] = Wl[(size_t)(k0 + r) * N + n0 + tx];
    __syncthreads();
    #pragma unroll
    for (int r = ty; r < 32; r += 8)
        WTl[(size_t)(n0 + r) * K + k0 + tx] = __float2half_rn(t[tx][r]);
}

// ---------------- layernorm (fp16 output) ----------------
__global__ __launch_bounds__(256) void ln_kernel(
    const float* __restrict__ x, const float* __restrict__ w,
    const float* __restrict__ b, __half* __restrict__ out)
{
    int row = blockIdx.x;
    const float* xr = x + (size_t)row * CDIM;
    float s = 0.f, s2 = 0.f;
    for (int i = threadIdx.x; i < CDIM; i += 256) {
        float v = xr[i]; s += v; s2 += v * v;
    }
    #pragma unroll
    for (int o = 16; o; o >>= 1) {
        s  += __shfl_xor_sync(0xffffffffu, s,  o);
        s2 += __shfl_xor_sync(0xffffffffu, s2, o);
    }
    __shared__ float rbuf[16];
    int wid = threadIdx.x >> 5, lane = threadIdx.x & 31;
    if (lane == 0) { rbuf[wid] = s; rbuf[8 + wid] = s2; }
    __syncthreads();
    float ts = 0.f, ts2 = 0.f;
    #pragma unroll
    for (int i = 0; i < 8; i++) { ts += rbuf[i]; ts2 += rbuf[8 + i]; }
    float mu  = ts * (1.0f / CDIM);
    float var = ts2 * (1.0f / CDIM) - mu * mu;
    float rs  = rsqrtf(var + 1e-5f);
    __half* orow = out + (size_t)row * CDIM;
    for (int i = threadIdx.x; i < CDIM; i += 256) {
        orow[i] = __float2half_rn((xr[i] - mu) * rs * w[i] + b[i]);
    }
}

// ---------------- final LN + head matvec ----------------
__global__ __launch_bounds__(256) void head_kernel(
    const float* __restrict__ x, const float* __restrict__ lw,
    const float* __restrict__ lb, const float* __restrict__ wh,
    float* __restrict__ out)
{
    int row = blockIdx.x;
    const float* xr = x + (size_t)row * CDIM;
    float s = 0.f, s2 = 0.f;
    for (int i = threadIdx.x; i < CDIM; i += 256) {
        float v = xr[i]; s += v; s2 += v * v;
    }
    #pragma unroll
    for (int o = 16; o; o >>= 1) {
        s  += __shfl_xor_sync(0xffffffffu, s,  o);
        s2 += __shfl_xor_sync(0xffffffffu, s2, o);
    }
    __shared__ float rbuf[16];
    int wid = threadIdx.x >> 5, lane = threadIdx.x & 31;
    if (lane == 0) { rbuf[wid] = s; rbuf[8 + wid] = s2; }
    __syncthreads();
    float ts = 0.f, ts2 = 0.f;
    #pragma unroll
    for (int i = 0; i < 8; i++) { ts += rbuf[i]; ts2 += rbuf[8 + i]; }
    float mu  = ts * (1.0f / CDIM);
    float var = ts2 * (1.0f / CDIM) - mu * mu;
    float rs  = rsqrtf(var + 1e-5f);

    float acc = 0.f;
    for (int i = threadIdx.x; i < CDIM; i += 256) {
        float hn = (xr[i] - mu) * rs * lw[i] + lb[i];
        acc += hn * wh[i];
    }
    #pragma unroll
    for (int o = 16; o; o >>= 1) acc += __shfl_xor_sync(0xffffffffu, acc, o);
    __syncthreads();
    if (lane == 0) rbuf[wid] = acc;
    __syncthreads();
    if (threadIdx.x == 0) {
        float t = 0.f;
        #pragma unroll
        for (int i = 0; i < 8; i++) t += rbuf[i];
        out[row] = t;
    }
}

// ======================= fp16 tensor-core GEMM (mma.sync) ====================
// C[M,N] = A[M,K] @ BT[N,K]^T.  A, BT fp16 K-major.
// Block 128x128, BK=32, 4 warps (2x2), warp tile 64x64, 4-stage cp.async,
// ONE __syncthreads per chunk.
// smem tile row = 64B (32 halves); swizzle: chunk16 ^= (row>>1)&3.
#define NSTAGE 4
#define STAGE_BYTES 16384             // A 8KB + B 8KB
#define HG_SMEM (NSTAGE*STAGE_BYTES)  // 65536

template <int EPI>  // 0=+bias->f32  1=+bias+residual->f32  2=+bias,gelu->f16
__global__ __launch_bounds__(128, 2) void hgemm(
    const __half* __restrict__ A, const __half* __restrict__ BT,
    const float* __restrict__ bias, const float* __restrict__ R,
    void* __restrict__ Cv, int M, int N, int K)
{
    extern __shared__ __align__(128) char smem[];
    uint32_t sbase = smem_u32(smem);
    int tid = threadIdx.x, lane = tid & 31, wid = tid >> 5;
    int wm = wid >> 1, wn = wid & 1;            // 2x2 warp grid
    int bm = blockIdx.y, bn = blockIdx.x;
    const __half* Ag = A  + (size_t)bm * 128 * K;
    const __half* Bg = BT + (size_t)bn * 128 * K;
    const int nch = K >> 5;

    float acc[4][8][4];
    #pragma unroll
    for (int i = 0; i < 4; i++)
        #pragma unroll
        for (int j = 0; j < 8; j++)
            #pragma unroll
            for (int q = 0; q < 4; q++) acc[i][j][q] = 0.f;

    // loader: 512 A + 512 B 16B-chunks; 128 threads x (4+4)
    #define LOADC(c, s)                                                        \
    {                                                                          \
        uint32_t st_ = sbase + (s) * STAGE_BYTES;                              \
        int k0_ = (c) * 32;                                                    \
        _Pragma("unroll")                                                      \
        for (int p = 0; p < 4; p++) {                                          \
            int j = tid + p * 128;                                             \
            int row = j >> 2, ch = j & 3;                                      \
            uint32_t off = row * 64 + 16 * (ch ^ ((row >> 1) & 3));            \
            cpa16(st_ + off, Ag + (size_t)row * K + k0_ + ch * 8);             \
            cpa16(st_ + 8192 + off, Bg + (size_t)row * K + k0_ + ch * 8);      \
        }                                                                      \
        CP_COMMIT();                                                           \
    }

    LOADC(0, 0); LOADC(1, 1); LOADC(2, 2);

    // ldmatrix lane->row/chunk mappings (hoisted)
    int rA = lane & 15;                         // row within 16-row A tile
    int hA = lane >> 4;                         // k-half selector
    int rB = ((lane >> 4) << 3) + (lane & 7);   // row within 16-row B pair
    int hB = (lane >> 3) & 1;

    uint32_t offA[4], xA[4], offB[4], xB[4];
    #pragma unroll
    for (int t4 = 0; t4 < 4; t4++) {
        int rowa = wm * 64 + t4 * 16 + rA;
        offA[t4] = rowa * 64;  xA[t4] = (rowa >> 1) & 3;
        int rowb = wn * 64 + t4 * 16 + rB;
        offB[t4] = rowb * 64;  xB[t4] = (rowb >> 1) & 3;
    }

    for (int c = 0; c < nch; c++) {
        CP_WAIT(2);
        __syncthreads();
        if (c + 3 < nch) { LOADC(c + 3, (c + 3) & 3); } else { CP_COMMIT(); }

        uint32_t abase = sbase + (c & 3) * STAGE_BYTES;
        uint32_t bbase = abase + 8192;

        #pragma unroll
        for (int ks = 0; ks < 2; ks++) {
            uint32_t afr[4][4];
            #pragma unroll
            for (int mt = 0; mt < 4; mt++) {
                uint32_t ad = abase + offA[mt] +
                              16 * (((uint32_t)(ks * 2 + hA)) ^ xA[mt]);
                LDMATRIX_X4(afr[mt][0], afr[mt][1], afr[mt][2], afr[mt][3], ad);
            }
            uint32_t bfr[8][2];
            #pragma unroll
            for (int pr = 0; pr < 4; pr++) {
                uint32_t bd = bbase + offB[pr] +
                              16 * (((uint32_t)(ks * 2 + hB)) ^ xB[pr]);
                uint32_t r0, r1, r2, r3;
                LDMATRIX_X4(r0, r1, r2, r3, bd);
                bfr[pr * 2][0] = r0;     bfr[pr * 2][1] = r1;
                bfr[pr * 2 + 1][0] = r2; bfr[pr * 2 + 1][1] = r3;
            }
            #pragma unroll
            for (int mt = 0; mt < 4; mt++)
                #pragma unroll
                for (int nt = 0; nt < 8; nt++)
                    MMA_F16(acc[mt][nt], afr[mt], bfr[nt]);
        }
    }

    // ---------------- epilogue ----------------
    int r0 = lane >> 2, c0 = lane & 3;
    #pragma unroll
    for (int mt = 0; mt < 4; mt++) {
        int row0 = bm * 128 + wm * 64 + mt * 16 + r0;
        #pragma unroll
        for (int nt = 0; nt < 8; nt++) {
            int col = bn * 128 + wn * 64 + nt * 8 + c0 * 2;
            float b0 = bias[col], b1 = bias[col + 1];
            float v00 = acc[mt][nt][0] + b0;
            float v01 = acc[mt][nt][1] + b1;
            float v10 = acc[mt][nt][2] + b0;
            float v11 = acc[mt][nt][3] + b1;
            if (EPI == 1) {
                float* C = (float*)Cv;
                const float* r0p = R + (size_t)row0 * N + col;
                const float* r1p = R + (size_t)(row0 + 8) * N + col;
                v00 += r0p[0]; v01 += r0p[1];
                v10 += r1p[0]; v11 += r1p[1];
                *(float2*)(C + (size_t)row0 * N + col) = make_float2(v00, v01);
                *(float2*)(C + (size_t)(row0 + 8) * N + col) = make_float2(v10, v11);
            } else if (EPI == 2) {
                __half* C = (__half*)Cv;
                __half2 o0 = __floats2half2_rn(gelu_tanh(v00), gelu_tanh(v01));
                __half2 o1 = __floats2half2_rn(gelu_tanh(v10), gelu_tanh(v11));
                *(__half2*)(C + (size_t)row0 * N + col) = o0;
                *(__half2*)(C + (size_t)(row0 + 8) * N + col) = o1;
            } else {
                float* C = (float*)Cv;
                *(float2*)(C + (size_t)row0 * N + col) = make_float2(v00, v01);
                *(float2*)(C + (size_t)(row0 + 8) * N + col) = make_float2(v10, v11);
            }
        }
    }
    #undef LOADC
}

// ---------------- flash attention (fp32 compute, fp16 output) ---------------
__global__ __launch_bounds__(256) void attn_kernel(
    const float* __restrict__ qkv, __half* __restrict__ y)
{
    extern __shared__ float sm[];
    float* Qs  = sm;                 // [64][65]
    float* Kts = Qs  + 64 * 65;      // [64 d][68]
    float* Vs  = Kts + 64 * 68;      // [64 kc][68]
    float* Ss  = Vs  + 64 * 68;      // [64 qr][68]

    int tid = threadIdx.x;
    int qt = blockIdx.x;
    int bh = blockIdx.y;
    int b = bh / HEADS, h = bh - (bh / HEADS) * HEADS;

    size_t rowbase = (size_t)b * TSEQ;
    int qoff = h * DHEAD;
    int koff = CDIM + h * DHEAD;
    int voff = 2 * CDIM + h * DHEAD;

    int lc  = (tid & 15) * 4;
    int lr0 = tid >> 4;

    #pragma unroll
    for (int rr = lr0; rr < 64; rr += 16) {
        float4 v = *(const float4*)(qkv + (rowbase + qt * 64 + rr) * C3 + qoff + lc);
        Qs[rr * 65 + lc + 0] = v.x;
        Qs[rr * 65 + lc + 1] = v.y;
        Qs[rr * 65 + lc + 2] = v.z;
        Qs[rr * 65 + lc + 3] = v.w;
    }

    int qr  = tid >> 2;
    int seg = tid & 3;
    int qg  = qt * 64 + qr;

    float m_i = -1e30f, l_i = 0.f;
    float O[16];
    #pragma unroll
    for (int i = 0; i < 16; i++) O[i] = 0.f;

    const float scale = 0.125f;

    for (int kt = 0; kt <= qt; kt++) {
        #pragma unroll
        for (int rr = lr0; rr < 64; rr += 16) {
            const float* base = qkv + (rowbase + kt * 64 + rr) * C3;
            float4 kv = *(const float4*)(base + koff + lc);
            Kts[(lc + 0) * 68 + rr] = kv.x;
            Kts[(lc + 1) * 68 + rr] = kv.y;
            Kts[(lc + 2) * 68 + rr] = kv.z;
            Kts[(lc + 3) * 68 + rr] = kv.w;
            float4 vv = *(const float4*)(base + voff + lc);
            Vs[rr * 68 + lc + 0] = vv.x;
            Vs[rr * 68 + lc + 1] = vv.y;
            Vs[rr * 68 + lc + 2] = vv.z;
            Vs[rr * 68 + lc + 3] = vv.w;
        }
        __syncthreads();

        float sacc[16];
        #pragma unroll
        for (int j = 0; j < 16; j++) sacc[j] = 0.f;
        const float* KtsBase = Kts + seg * 16;
        const float* Qrow = Qs + qr * 65;
        #pragma unroll 8
        for (int d = 0; d < 64; d++) {
            float qv = Qrow[d];
            float4 k0 = *(const float4*)(KtsBase + d * 68 + 0);
            float4 k1 = *(const float4*)(KtsBase + d * 68 + 4);
            float4 k2 = *(const float4*)(KtsBase + d * 68 + 8);
            float4 k3 = *(const float4*)(KtsBase + d * 68 + 12);
            sacc[0]  += qv * k0.x; sacc[1]  += qv * k0.y;
            sacc[2]  += qv * k0.z; sacc[3]  += qv * k0.w;
            sacc[4]  += qv * k1.x; sacc[5]  += qv * k1.y;
            sacc[6]  += qv * k1.z; sacc[7]  += qv * k1.w;
            sacc[8]  += qv * k2.x; sacc[9]  += qv * k2.y;
            sacc[10] += qv * k2.z; sacc[11] += qv * k2.w;
            sacc[12] += qv * k3.x; sacc[13] += qv * k3.y;
            sacc[14] += qv * k3.z; sacc[15] += qv * k3.w;
        }

        float mblk = -1e30f;
        #pragma unroll
        for (int j = 0; j < 16; j++) {
            int kg = kt * 64 + seg * 16 + j;
            float s = sacc[j] * scale;
            if (kg > qg) s = -1e30f;
            sacc[j] = s;
            mblk = fmaxf(mblk, s);
        }
        mblk = fmaxf(mblk, __shfl_xor_sync(0xffffffffu, mblk, 1));
        mblk = fmaxf(mblk, __shfl_xor_sync(0xffffffffu, mblk, 2));
        float m_new = fmaxf(m_i, mblk);
        float alpha = __expf(m_i - m_new);
        float lblk = 0.f;
        #pragma unroll
        for (int j = 0; j < 16; j++) {
            float p = __expf(sacc[j] - m_new);
            sacc[j] = p;
            lblk += p;
        }
        lblk += __shfl_xor_sync(0xffffffffu, lblk, 1);
        lblk += __shfl_xor_sync(0xffffffffu, lblk, 2);
        l_i = l_i * alpha + lblk;
        m_i = m_new;

        #pragma unroll
        for (int j = 0; j < 16; j++)
            Ss[qr * 68 + seg * 16 + j] = sacc[j];
        __syncthreads();

        #pragma unroll
        for (int i = 0; i < 16; i++) O[i] *= alpha;
        const float* VsBase = Vs + seg * 16;
        const float* Srow = Ss + qr * 68;
        #pragma unroll 4
        for (int j = 0; j < 64; j++) {
            float s = Srow[j];
            float4 v0 = *(const float4*)(VsBase + j * 68 + 0);
            float4 v1 = *(const float4*)(VsBase + j * 68 + 4);
            float4 v2 = *(const float4*)(VsBase + j * 68 + 8);
            float4 v3 = *(const float4*)(VsBase + j * 68 + 12);
            O[0]  += s * v0.x; O[1]  += s * v0.y; O[2]  += s * v0.z; O[3]  += s * v0.w;
            O[4]  += s * v1.x; O[5]  += s * v1.y; O[6]  += s * v1.z; O[7]  += s * v1.w;
            O[8]  += s * v2.x; O[9]  += s * v2.y; O[10] += s * v2.z; O[11] += s * v2.w;
            O[12] += s * v3.x; O[13] += s * v3.y; O[14] += s * v3.z; O[15] += s * v3.w;
        }
        __syncthreads();
    }

    float inv = 1.f / l_i;
    __half* yrow = y + (rowbase + qt * 64 + qr) * CDIM + h * DHEAD + seg * 16;
    __half2 pk[8];
    #pragma unroll
    for (int i = 0; i < 8; i++)
        pk[i] = __floats2half2_rn(O[2 * i] * inv, O[2 * i + 1] * inv);
    *(uint4*)(yrow)     = *(uint4*)&pk[0];
    *(uint4*)(yrow + 8) = *(uint4*)&pk[4];
}

// ---------------- launch ----------------
extern "C" void kernel_launch(void* const* d_in, const int* in_sizes, int n_in,
                              void* d_out, int out_size)
{
    const int*   idx    = (const int*)  d_in[0];
    const float* wte    = (const float*)d_in[1];
    const float* wpe    = (const float*)d_in[2];
    const float* ln1_w  = (const float*)d_in[3];
    const float* ln1_b  = (const float*)d_in[4];
    const float* w_qkv  = (const float*)d_in[5];
    const float* b_qkv  = (const float*)d_in[6];
    const float* w_ao   = (const float*)d_in[7];
    const float* b_ao   = (const float*)d_in[8];
    const float* ln2_w  = (const float*)d_in[9];
    const float* ln2_b  = (const float*)d_in[10];
    const float* w_fc   = (const float*)d_in[11];
    const float* b_fc   = (const float*)d_in[12];
    const float* w_fp   = (const float*)d_in[13];
    const float* b_fp   = (const float*)d_in[14];
    const float* lnf_w  = (const float*)d_in[15];
    const float* lnf_b  = (const float*)d_in[16];
    const float* w_head = (const float*)d_in[17];
    float* out = (float*)d_out;

    float *x, *qkvb;
    __half *hh, *yh, *fch, *wqkvT, *waoT, *wfcT, *wfpT;
    cudaGetSymbolAddress((void**)&x,    g_x);
    cudaGetSymbolAddress((void**)&qkvb, g_qkv);
    cudaGetSymbolAddress((void**)&hh,   g_h);
    cudaGetSymbolAddress((void**)&yh,   g_y);
    cudaGetSymbolAddress((void**)&fch,  g_fc);
    cudaGetSymbolAddress((void**)&wqkvT, g_wqkvT);
    cudaGetSymbolAddress((void**)&waoT,  g_waoT);
    cudaGetSymbolAddress((void**)&wfcT,  g_wfcT);
    cudaGetSymbolAddress((void**)&wfpT,  g_wfpT);

    const int attn_smem = (64 * 65 + 64 * 68 + 64 * 68 + 64 * 68) * sizeof(float);
    cudaFuncSetAttribute(attn_kernel, cudaFuncAttributeMaxDynamicSharedMemorySize, attn_smem);
    cudaFuncSetAttribute(hgemm<0>, cudaFuncAttributeMaxDynamicSharedMemorySize, HG_SMEM);
    cudaFuncSetAttribute(hgemm<1>, cudaFuncAttributeMaxDynamicSharedMemorySize, HG_SMEM);
    cudaFuncSetAttribute(hgemm<2>, cudaFuncAttributeMaxDynamicSharedMemorySize, HG_SMEM);

    // transpose + fp16-round all weights (once per call)
    transpose_kernel<<<dim3(C3 / 32, CDIM / 32, LAYERS), 256>>>(w_qkv, wqkvT, CDIM, C3);
    transpose_kernel<<<dim3(CDIM / 32, CDIM / 32, LAYERS), 256>>>(w_ao, waoT, CDIM, CDIM);
    transpose_kernel<<<dim3(C4 / 32, CDIM / 32, LAYERS), 256>>>(w_fc, wfcT, CDIM, C4);
    transpose_kernel<<<dim3(CDIM / 32, C4 / 32, LAYERS), 256>>>(w_fp, wfpT, C4, CDIM);

    embed_kernel<<<(MROWS * CDIM) / 256, 256>>>(idx, wte, wpe, x);

    for (int l = 0; l < LAYERS; l++) {
        ln_kernel<<<MROWS, 256>>>(x, ln1_w + l * CDIM, ln1_b + l * CDIM, hh);
        hgemm<0><<<dim3(C3 / 128, MROWS / 128), 128, HG_SMEM>>>(
            hh, wqkvT + (size_t)l * C3 * CDIM, b_qkv + l * C3, nullptr, qkvb,
            MROWS, C3, CDIM);
        attn_kernel<<<dim3(TSEQ / 64, BATCH * HEADS), 256, attn_smem>>>(qkvb, yh);
        hgemm<1><<<dim3(CDIM / 128, MROWS / 128), 128, HG_SMEM>>>(
            yh, waoT + (size_t)l * CDIM * CDIM, b_ao + l * CDIM, x, x,
            MROWS, CDIM, CDIM);
        ln_kernel<<<MROWS, 256>>>(x, ln2_w + l * CDIM, ln2_b + l * CDIM, hh);
        hgemm<2><<<dim3(C4 / 128, MROWS / 128), 128, HG_SMEM>>>(
            hh, wfcT + (size_t)l * C4 * CDIM, b_fc + l * C4, nullptr, fch,
            MROWS, C4, CDIM);
        hgemm<1><<<dim3(CDIM / 128, MROWS / 128), 128, HG_SMEM>>>(
            fch, wfpT + (size_t)l * CDIM * C4, b_fp + l * CDIM, x, x,
            MROWS, CDIM, C4);
    }

    head_kernel<<<MROWS, 256>>>(x, lnf_w, lnf_b, w_head, out);
}

// round 6
// speedup vs baseline: 9.9097x; 4.8844x over previous
#include <cuda_runtime.h>
#include <cuda_fp16.h>
#include <math.h>
#include <stdint.h>

// ---------------- problem constants ----------------
#define LAYERS 12
#define HEADS  12
#define CDIM   768
#define TSEQ   1024
#define BATCH  4
#define MROWS  (BATCH*TSEQ)      // 4096
#define C3     (3*CDIM)          // 2304
#define C4     (4*CDIM)          // 3072
#define DHEAD  64

// ---------------- scratch (device globals: no allocation allowed) ----------
__device__ float  g_x  [MROWS*CDIM];          // fp32 residual stream
__device__ __half g_qkv[MROWS*C3];            // fp16 qkv
__device__ __half g_h  [MROWS*CDIM];          // fp16 LN output (GEMM A)
__device__ __half g_y  [MROWS*CDIM];          // fp16 attention output
__device__ __half g_fc [MROWS*C4];            // fp16 gelu output
// transposed (to [N,K] K-major) fp16 weights
__device__ __half g_wqkvT[LAYERS*C3*CDIM];
__device__ __half g_waoT [LAYERS*CDIM*CDIM];
__device__ __half g_wfcT [LAYERS*C4*CDIM];
__device__ __half g_wfpT [LAYERS*CDIM*C4];

// ---------------- helpers ----------------
__device__ __forceinline__ uint32_t smem_u32(const void* p) {
    uint32_t a;
    asm("{ .reg .u64 t; cvta.to.shared.u64 t, %1; cvt.u32.u64 %0, t; }"
        : "=r"(a) : "l"(p));
    return a;
}
__device__ __forceinline__ void cpa16(uint32_t saddr, const void* g) {
    asm volatile("cp.async.cg.shared.global [%0], [%1], 16;" :: "r"(saddr), "l"(g));
}
#define CP_COMMIT()  asm volatile("cp.async.commit_group;" ::: "memory")
#define CP_WAIT(n)   asm volatile("cp.async.wait_group %0;" :: "n"(n) : "memory")

#define LDMATRIX_X4(r0, r1, r2, r3, addr) \
    asm volatile("ldmatrix.sync.aligned.m8n8.x4.shared.b16 {%0,%1,%2,%3}, [%4];" \
        : "=r"(r0), "=r"(r1), "=r"(r2), "=r"(r3) : "r"(addr))

#define LDMATRIX_X4_T(r0, r1, r2, r3, addr) \
    asm volatile("ldmatrix.sync.aligned.m8n8.x4.trans.shared.b16 {%0,%1,%2,%3}, [%4];" \
        : "=r"(r0), "=r"(r1), "=r"(r2), "=r"(r3) : "r"(addr))

#define MMA_F16(d, a0, a1, a2, a3, b0, b1) \
    asm volatile( \
        "mma.sync.aligned.m16n8k16.row.col.f32.f16.f16.f32 " \
        "{%0,%1,%2,%3},{%4,%5,%6,%7},{%8,%9},{%0,%1,%2,%3};" \
        : "+f"((d)[0]), "+f"((d)[1]), "+f"((d)[2]), "+f"((d)[3]) \
        : "r"(a0), "r"(a1), "r"(a2), "r"(a3), "r"(b0), "r"(b1))

__device__ __forceinline__ uint32_t packh2(float lo, float hi) {
    __half2 h = __floats2half2_rn(lo, hi);
    return *(uint32_t*)&h;
}

__device__ __forceinline__ float gelu_tanh(float v) {
    float c = 0.7978845608028654f * (v + 0.044715f * v * v * v);
    return 0.5f * v * (1.0f + tanhf(c));
}

// ---------------- embedding ----------------
__global__ __launch_bounds__(256) void embed_kernel(
    const int* __restrict__ idx, const float* __restrict__ wte,
    const float* __restrict__ wpe, float* __restrict__ x)
{
    int i = blockIdx.x * 256 + threadIdx.x;
    int row = i / CDIM;
    int c   = i - row * CDIM;
    int t   = row & (TSEQ - 1);
    int id  = idx[row];
    x[i] = wte[(size_t)id * CDIM + c] + wpe[(size_t)t * CDIM + c];
}

// ---------------- weight transpose (fp32 [K,N] -> fp16 [N,K]) --------------
__global__ __launch_bounds__(256) void transpose_kernel(
    const float* __restrict__ W, __half* __restrict__ WT, int K, int N)
{
    __shared__ float t[32][33];
    int l = blockIdx.z;
    const float* Wl = W + (size_t)l * K * N;
    __half* WTl = WT + (size_t)l * N * K;
    int k0 = blockIdx.y * 32, n0 = blockIdx.x * 32;
    int tx = threadIdx.x & 31, ty = threadIdx.x >> 5;   // 32 x 8
    #pragma unroll
    for (int r = ty; r < 32; r += 8)
        t[r][tx] = Wl[(size_t)(k0 + r) * N + n0 + tx];
    __syncthreads();
    #pragma unroll
    for (int r = ty; r < 32; r += 8)
        WTl[(size_t)(n0 + r) * K + k0 + tx] = __float2half_rn(t[tx][r]);
}

// ---------------- layernorm (fp16 output) ----------------
__global__ __launch_bounds__(256) void ln_kernel(
    const float* __restrict__ x, const float* __restrict__ w,
    const float* __restrict__ b, __half* __restrict__ out)
{
    int row = blockIdx.x;
    const float* xr = x + (size_t)row * CDIM;
    float s = 0.f, s2 = 0.f;
    for (int i = threadIdx.x; i < CDIM; i += 256) {
        float v = xr[i]; s += v; s2 += v * v;
    }
    #pragma unroll
    for (int o = 16; o; o >>= 1) {
        s  += __shfl_xor_sync(0xffffffffu, s,  o);
        s2 += __shfl_xor_sync(0xffffffffu, s2, o);
    }
    __shared__ float rbuf[16];
    int wid = threadIdx.x >> 5, lane = threadIdx.x & 31;
    if (lane == 0) { rbuf[wid] = s; rbuf[8 + wid] = s2; }
    __syncthreads();
    float ts = 0.f, ts2 = 0.f;
    #pragma unroll
    for (int i = 0; i < 8; i++) { ts += rbuf[i]; ts2 += rbuf[8 + i]; }
    float mu  = ts * (1.0f / CDIM);
    float var = ts2 * (1.0f / CDIM) - mu * mu;
    float rs  = rsqrtf(var + 1e-5f);
    __half* orow = out + (size_t)row * CDIM;
    for (int i = threadIdx.x; i < CDIM; i += 256) {
        orow[i] = __float2half_rn((xr[i] - mu) * rs * w[i] + b[i]);
    }
}

// ---------------- final LN + head matvec ----------------
__global__ __launch_bounds__(256) void head_kernel(
    const float* __restrict__ x, const float* __restrict__ lw,
    const float* __restrict__ lb, const float* __restrict__ wh,
    float* __restrict__ out)
{
    int row = blockIdx.x;
    const float* xr = x + (size_t)row * CDIM;
    float s = 0.f, s2 = 0.f;
    for (int i = threadIdx.x; i < CDIM; i += 256) {
        float v = xr[i]; s += v; s2 += v * v;
    }
    #pragma unroll
    for (int o = 16; o; o >>= 1) {
        s  += __shfl_xor_sync(0xffffffffu, s,  o);
        s2 += __shfl_xor_sync(0xffffffffu, s2, o);
    }
    __shared__ float rbuf[16];
    int wid = threadIdx.x >> 5, lane = threadIdx.x & 31;
    if (lane == 0) { rbuf[wid] = s; rbuf[8 + wid] = s2; }
    __syncthreads();
    float ts = 0.f, ts2 = 0.f;
    #pragma unroll
    for (int i = 0; i < 8; i++) { ts += rbuf[i]; ts2 += rbuf[8 + i]; }
    float mu  = ts * (1.0f / CDIM);
    float var = ts2 * (1.0f / CDIM) - mu * mu;
    float rs  = rsqrtf(var + 1e-5f);

    float acc = 0.f;
    for (int i = threadIdx.x; i < CDIM; i += 256) {
        float hn = (xr[i] - mu) * rs * lw[i] + lb[i];
        acc += hn * wh[i];
    }
    #pragma unroll
    for (int o = 16; o; o >>= 1) acc += __shfl_xor_sync(0xffffffffu, acc, o);
    __syncthreads();
    if (lane == 0) rbuf[wid] = acc;
    __syncthreads();
    if (threadIdx.x == 0) {
        float t = 0.f;
        #pragma unroll
        for (int i = 0; i < 8; i++) t += rbuf[i];
        out[row] = t;
    }
}

// ======================= fp16 tensor-core GEMM (mma.sync) ====================
// Block 128x128, BK=32, 4 warps (2x2), warp tile 64x64, 4-stage cp.async.
#define NSTAGE 4
#define STAGE_BYTES 16384
#define HG_SMEM (NSTAGE*STAGE_BYTES)

template <int EPI>  // 0=+bias->f32  1=+bias+res->f32  2=+bias,gelu->f16  3=+bias->f16
__global__ __launch_bounds__(128, 2) void hgemm(
    const __half* __restrict__ A, const __half* __restrict__ BT,
    const float* __restrict__ bias, const float* __restrict__ R,
    void* __restrict__ Cv, int M, int N, int K)
{
    extern __shared__ __align__(128) char smem[];
    uint32_t sbase = smem_u32(smem);
    int tid = threadIdx.x, lane = tid & 31, wid = tid >> 5;
    int wm = wid >> 1, wn = wid & 1;
    int bm = blockIdx.y, bn = blockIdx.x;
    const __half* Ag = A  + (size_t)bm * 128 * K;
    const __half* Bg = BT + (size_t)bn * 128 * K;
    const int nch = K >> 5;

    float acc[4][8][4];
    #pragma unroll
    for (int i = 0; i < 4; i++)
        #pragma unroll
        for (int j = 0; j < 8; j++)
            #pragma unroll
            for (int q = 0; q < 4; q++) acc[i][j][q] = 0.f;

    #define LOADC(c, s)                                                        \
    {                                                                          \
        uint32_t st_ = sbase + (s) * STAGE_BYTES;                              \
        int k0_ = (c) * 32;                                                    \
        _Pragma("unroll")                                                      \
        for (int p = 0; p < 4; p++) {                                          \
            int j = tid + p * 128;                                             \
            int row = j >> 2, ch = j & 3;                                      \
            uint32_t off = row * 64 + 16 * (ch ^ ((row >> 1) & 3));            \
            cpa16(st_ + off, Ag + (size_t)row * K + k0_ + ch * 8);             \
            cpa16(st_ + 8192 + off, Bg + (size_t)row * K + k0_ + ch * 8);      \
        }                                                                      \
        CP_COMMIT();                                                           \
    }

    LOADC(0, 0); LOADC(1, 1); LOADC(2, 2);

    int rA = lane & 15;
    int hA = lane >> 4;
    int rB = ((lane >> 4) << 3) + (lane & 7);
    int hB = (lane >> 3) & 1;

    uint32_t offA[4], xA[4], offB[4], xB[4];
    #pragma unroll
    for (int t4 = 0; t4 < 4; t4++) {
        int rowa = wm * 64 + t4 * 16 + rA;
        offA[t4] = rowa * 64;  xA[t4] = (rowa >> 1) & 3;
        int rowb = wn * 64 + t4 * 16 + rB;
        offB[t4] = rowb * 64;  xB[t4] = (rowb >> 1) & 3;
    }

    for (int c = 0; c < nch; c++) {
        CP_WAIT(2);
        __syncthreads();
        if (c + 3 < nch) { LOADC(c + 3, (c + 3) & 3); } else { CP_COMMIT(); }

        uint32_t abase = sbase + (c & 3) * STAGE_BYTES;
        uint32_t bbase = abase + 8192;

        #pragma unroll
        for (int ks = 0; ks < 2; ks++) {
            uint32_t afr[4][4];
            #pragma unroll
            for (int mt = 0; mt < 4; mt++) {
                uint32_t ad = abase + offA[mt] +
                              16 * (((uint32_t)(ks * 2 + hA)) ^ xA[mt]);
                LDMATRIX_X4(afr[mt][0], afr[mt][1], afr[mt][2], afr[mt][3], ad);
            }
            uint32_t bfr[8][2];
            #pragma unroll
            for (int pr = 0; pr < 4; pr++) {
                uint32_t bd = bbase + offB[pr] +
                              16 * (((uint32_t)(ks * 2 + hB)) ^ xB[pr]);
                uint32_t r0, r1, r2, r3;
                LDMATRIX_X4(r0, r1, r2, r3, bd);
                bfr[pr * 2][0] = r0;     bfr[pr * 2][1] = r1;
                bfr[pr * 2 + 1][0] = r2; bfr[pr * 2 + 1][1] = r3;
            }
            #pragma unroll
            for (int mt = 0; mt < 4; mt++)
                #pragma unroll
                for (int nt = 0; nt < 8; nt++)
                    MMA_F16(acc[mt][nt], afr[mt][0], afr[mt][1], afr[mt][2],
                            afr[mt][3], bfr[nt][0], bfr[nt][1]);
        }
    }

    int r0 = lane >> 2, c0 = lane & 3;
    #pragma unroll
    for (int mt = 0; mt < 4; mt++) {
        int row0 = bm * 128 + wm * 64 + mt * 16 + r0;
        #pragma unroll
        for (int nt = 0; nt < 8; nt++) {
            int col = bn * 128 + wn * 64 + nt * 8 + c0 * 2;
            float b0 = bias[col], b1 = bias[col + 1];
            float v00 = acc[mt][nt][0] + b0;
            float v01 = acc[mt][nt][1] + b1;
            float v10 = acc[mt][nt][2] + b0;
            float v11 = acc[mt][nt][3] + b1;
            if (EPI == 1) {
                float* C = (float*)Cv;
                const float* r0p = R + (size_t)row0 * N + col;
                const float* r1p = R + (size_t)(row0 + 8) * N + col;
                v00 += r0p[0]; v01 += r0p[1];
                v10 += r1p[0]; v11 += r1p[1];
                *(float2*)(C + (size_t)row0 * N + col) = make_float2(v00, v01);
                *(float2*)(C + (size_t)(row0 + 8) * N + col) = make_float2(v10, v11);
            } else if (EPI == 2) {
                __half* C = (__half*)Cv;
                __half2 o0 = __floats2half2_rn(gelu_tanh(v00), gelu_tanh(v01));
                __half2 o1 = __floats2half2_rn(gelu_tanh(v10), gelu_tanh(v11));
                *(__half2*)(C + (size_t)row0 * N + col) = o0;
                *(__half2*)(C + (size_t)(row0 + 8) * N + col) = o1;
            } else if (EPI == 3) {
                __half* C = (__half*)Cv;
                *(__half2*)(C + (size_t)row0 * N + col) = __floats2half2_rn(v00, v01);
                *(__half2*)(C + (size_t)(row0 + 8) * N + col) = __floats2half2_rn(v10, v11);
            } else {
                float* C = (float*)Cv;
                *(float2*)(C + (size_t)row0 * N + col) = make_float2(v00, v01);
                *(float2*)(C + (size_t)(row0 + 8) * N + col) = make_float2(v10, v11);
            }
        }
    }
    #undef LOADC
}

// ================= fp16 tensor-core flash attention =================
// grid (16 qtiles, 48 b*h), block 128 (4 warps, each owns 16 q-rows).
// Q/K/V fp16 smem tiles 64x64 (128B rows, chunk16 ^= row&7), K/V double-buffered.
// S and O accumulate fp32 in mma; softmax fp32.
#define AT_SMEM (8192 + 2*16384)   // Q + 2 stages of (K+V)

__global__ __launch_bounds__(128) void attn_mma(
    const __half* __restrict__ qkv, __half* __restrict__ y)
{
    extern __shared__ __align__(128) char smem[];
    uint32_t sb = smem_u32(smem);
    int tid = threadIdx.x, lane = tid & 31, w = tid >> 5;
    int qt = blockIdx.x;
    int bh = blockIdx.y;
    int b = bh / HEADS, h = bh - (bh / HEADS) * HEADS;
    const __half* base = qkv + (size_t)b * TSEQ * C3;
    int qcol = h * DHEAD, kcol = CDIM + h * DHEAD, vcol = 2 * CDIM + h * DHEAD;

    #define SWOFF(row, ch) ((uint32_t)((row) * 128 + 16 * ((ch) ^ ((row) & 7))))

    // Q load (rows qt*64 .. +63)
    {
        #pragma unroll
        for (int p = 0; p < 4; p++) {
            int j = tid + p * 128;
            int row = j >> 3, ch = j & 7;
            cpa16(sb + SWOFF(row, ch),
                  base + (size_t)(qt * 64 + row) * C3 + qcol + ch * 8);
        }
    }
    #define LOADKV(kt, s)                                                      \
    {                                                                          \
        uint32_t kb_ = sb + 8192 + (s) * 16384;                                \
        _Pragma("unroll")                                                      \
        for (int p = 0; p < 4; p++) {                                          \
            int j = tid + p * 128;                                             \
            int row = j >> 3, ch = j & 7;                                      \
            const __half* rp = base + (size_t)((kt) * 64 + row) * C3;          \
            cpa16(kb_ + SWOFF(row, ch), rp + kcol + ch * 8);                   \
            cpa16(kb_ + 8192 + SWOFF(row, ch), rp + vcol + ch * 8);            \
        }                                                                      \
    }
    LOADKV(0, 0);
    CP_COMMIT();   // group: Q + K0 + V0

    float m0 = -1e30f, m1 = -1e30f, l0 = 0.f, l1 = 0.f;
    float o[8][4];
    #pragma unroll
    for (int i = 0; i < 8; i++)
        #pragma unroll
        for (int q = 0; q < 4; q++) o[i][q] = 0.f;

    uint32_t qfr[4][4];
    int rqA = w * 16 + (lane & 15);     // Q ldmatrix row
    int hA  = lane >> 4;
    int rB  = ((lane >> 4) << 3) + (lane & 7);   // K ldmatrix row-in-16
    int hB  = (lane >> 3) & 1;
    int rV  = ((lane >> 3) & 1) * 8 + (lane & 7); // V trans row-in-16
    int hV  = lane >> 4;

    int r0loc = (lane >> 2);
    int r0g = qt * 64 + w * 16 + r0loc;  // global q row (c0/c1); +8 for c2/c3
    int cq = lane & 3;

    for (int kt = 0; kt <= qt; kt++) {
        __syncthreads();
        if (kt + 1 <= qt) { LOADKV(kt + 1, (kt + 1) & 1); CP_COMMIT(); }
        else { CP_COMMIT(); }
        CP_WAIT(1);
        __syncthreads();

        if (kt == 0) {
            #pragma unroll
            for (int ks = 0; ks < 4; ks++) {
                uint32_t ad = sb + SWOFF(rqA, (ks * 2 + hA) ^ 0) ;
                // SWOFF already folds in row-xor; recompute properly:
                ad = sb + (uint32_t)(rqA * 128 + 16 * ((ks * 2 + hA) ^ (rqA & 7)));
                LDMATRIX_X4(qfr[ks][0], qfr[ks][1], qfr[ks][2], qfr[ks][3], ad);
            }
        }

        uint32_t kb = sb + 8192 + (kt & 1) * 16384;
        uint32_t vb = kb + 8192;

        // ---- S = Q K^T ----
        float s_acc[8][4];
        #pragma unroll
        for (int i = 0; i < 8; i++)
            #pragma unroll
            for (int q = 0; q < 4; q++) s_acc[i][q] = 0.f;

        #pragma unroll
        for (int ks = 0; ks < 4; ks++) {
            #pragma unroll
            for (int pr = 0; pr < 4; pr++) {
                int row = pr * 16 + rB;
                uint32_t bd = kb + (uint32_t)(row * 128 +
                              16 * ((ks * 2 + hB) ^ (row & 7)));
                uint32_t b0, b1, b2, b3;
                LDMATRIX_X4(b0, b1, b2, b3, bd);
                MMA_F16(s_acc[pr * 2],     qfr[ks][0], qfr[ks][1], qfr[ks][2], qfr[ks][3], b0, b1);
                MMA_F16(s_acc[pr * 2 + 1], qfr[ks][0], qfr[ks][1], qfr[ks][2], qfr[ks][3], b2, b3);
            }
        }

        // ---- mask + online softmax (fp32) ----
        bool diag = (kt == qt);
        float mx0 = -1e30f, mx1 = -1e30f;
        #pragma unroll
        for (int nt = 0; nt < 8; nt++) {
            #pragma unroll
            for (int j = 0; j < 2; j++) {
                int col = kt * 64 + nt * 8 + cq * 2 + j;
                float s0 = s_acc[nt][j] * 0.125f;
                float s1 = s_acc[nt][2 + j] * 0.125f;
                if (diag && col > r0g)     s0 = -1e30f;
                if (diag && col > r0g + 8) s1 = -1e30f;
                s_acc[nt][j] = s0; s_acc[nt][2 + j] = s1;
                mx0 = fmaxf(mx0, s0); mx1 = fmaxf(mx1, s1);
            }
        }
        mx0 = fmaxf(mx0, __shfl_xor_sync(0xffffffffu, mx0, 1));
        mx0 = fmaxf(mx0, __shfl_xor_sync(0xffffffffu, mx0, 2));
        mx1 = fmaxf(mx1, __shfl_xor_sync(0xffffffffu, mx1, 1));
        mx1 = fmaxf(mx1, __shfl_xor_sync(0xffffffffu, mx1, 2));
        float mn0 = fmaxf(m0, mx0), mn1 = fmaxf(m1, mx1);
        float a0 = __expf(m0 - mn0), a1 = __expf(m1 - mn1);
        float sum0 = 0.f, sum1 = 0.f;
        #pragma unroll
        for (int nt = 0; nt < 8; nt++) {
            #pragma unroll
            for (int j = 0; j < 2; j++) {
                float p0 = __expf(s_acc[nt][j] - mn0);
                float p1 = __expf(s_acc[nt][2 + j] - mn1);
                s_acc[nt][j] = p0; s_acc[nt][2 + j] = p1;
                sum0 += p0; sum1 += p1;
            }
        }
        sum0 += __shfl_xor_sync(0xffffffffu, sum0, 1);
        sum0 += __shfl_xor_sync(0xffffffffu, sum0, 2);
        sum1 += __shfl_xor_sync(0xffffffffu, sum1, 1);
        sum1 += __shfl_xor_sync(0xffffffffu, sum1, 2);
        l0 = l0 * a0 + sum0; l1 = l1 * a1 + sum1;
        m0 = mn0; m1 = mn1;

        #pragma unroll
        for (int nt = 0; nt < 8; nt++) {
            o[nt][0] *= a0; o[nt][1] *= a0;
            o[nt][2] *= a1; o[nt][3] *= a1;
        }

        // pack P to fp16 a-fragments
        uint32_t pa[4][4];
        #pragma unroll
        for (int kv = 0; kv < 4; kv++) {
            pa[kv][0] = packh2(s_acc[2 * kv][0],     s_acc[2 * kv][1]);
            pa[kv][1] = packh2(s_acc[2 * kv][2],     s_acc[2 * kv][3]);
            pa[kv][2] = packh2(s_acc[2 * kv + 1][0], s_acc[2 * kv + 1][1]);
            pa[kv][3] = packh2(s_acc[2 * kv + 1][2], s_acc[2 * kv + 1][3]);
        }

        // ---- O += P V ----
        #pragma unroll
        for (int kv = 0; kv < 4; kv++) {
            #pragma unroll
            for (int dt = 0; dt < 4; dt++) {
                int row = kv * 16 + rV;
                uint32_t vd = vb + (uint32_t)(row * 128 +
                              16 * ((dt * 2 + hV) ^ (row & 7)));
                uint32_t b0, b1, b2, b3;
                LDMATRIX_X4_T(b0, b1, b2, b3, vd);
                MMA_F16(o[dt * 2],     pa[kv][0], pa[kv][1], pa[kv][2], pa[kv][3], b0, b1);
                MMA_F16(o[dt * 2 + 1], pa[kv][0], pa[kv][1], pa[kv][2], pa[kv][3], b2, b3);
            }
        }
    }

    // ---- epilogue ----
    float inv0 = 1.f / l0, inv1 = 1.f / l1;
    size_t row0 = (size_t)b * TSEQ + qt * 64 + w * 16 + r0loc;
    __half* y0 = y + row0 * CDIM + h * DHEAD + cq * 2;
    __half* y1 = y0 + 8 * CDIM;
    #pragma unroll
    for (int nt = 0; nt < 8; nt++) {
        *(__half2*)(y0 + nt * 8) = __floats2half2_rn(o[nt][0] * inv0, o[nt][1] * inv0);
        *(__half2*)(y1 + nt * 8) = __floats2half2_rn(o[nt][2] * inv1, o[nt][3] * inv1);
    }
    #undef LOADKV
    #undef SWOFF
}

// ---------------- launch ----------------
extern "C" void kernel_launch(void* const* d_in, const int* in_sizes, int n_in,
                              void* d_out, int out_size)
{
    const int*   idx    = (const int*)  d_in[0];
    const float* wte    = (const float*)d_in[1];
    const float* wpe    = (const float*)d_in[2];
    const float* ln1_w  = (const float*)d_in[3];
    const float* ln1_b  = (const float*)d_in[4];
    const float* w_qkv  = (const float*)d_in[5];
    const float* b_qkv  = (const float*)d_in[6];
    const float* w_ao   = (const float*)d_in[7];
    const float* b_ao   = (const float*)d_in[8];
    const float* ln2_w  = (const float*)d_in[9];
    const float* ln2_b  = (const float*)d_in[10];
    const float* w_fc   = (const float*)d_in[11];
    const float* b_fc   = (const float*)d_in[12];
    const float* w_fp   = (const float*)d_in[13];
    const float* b_fp   = (const float*)d_in[14];
    const float* lnf_w  = (const float*)d_in[15];
    const float* lnf_b  = (const float*)d_in[16];
    const float* w_head = (const float*)d_in[17];
    float* out = (float*)d_out;

    float *x;
    __half *qkvh, *hh, *yh, *fch, *wqkvT, *waoT, *wfcT, *wfpT;
    cudaGetSymbolAddress((void**)&x,    g_x);
    cudaGetSymbolAddress((void**)&qkvh, g_qkv);
    cudaGetSymbolAddress((void**)&hh,   g_h);
    cudaGetSymbolAddress((void**)&yh,   g_y);
    cudaGetSymbolAddress((void**)&fch,  g_fc);
    cudaGetSymbolAddress((void**)&wqkvT, g_wqkvT);
    cudaGetSymbolAddress((void**)&waoT,  g_waoT);
    cudaGetSymbolAddress((void**)&wfcT,  g_wfcT);
    cudaGetSymbolAddress((void**)&wfpT,  g_wfpT);

    cudaFuncSetAttribute(attn_mma, cudaFuncAttributeMaxDynamicSharedMemorySize, AT_SMEM);
    cudaFuncSetAttribute(hgemm<1>, cudaFuncAttributeMaxDynamicSharedMemorySize, HG_SMEM);
    cudaFuncSetAttribute(hgemm<2>, cudaFuncAttributeMaxDynamicSharedMemorySize, HG_SMEM);
    cudaFuncSetAttribute(hgemm<3>, cudaFuncAttributeMaxDynamicSharedMemorySize, HG_SMEM);

    transpose_kernel<<<dim3(C3 / 32, CDIM / 32, LAYERS), 256>>>(w_qkv, wqkvT, CDIM, C3);
    transpose_kernel<<<dim3(CDIM / 32, CDIM / 32, LAYERS), 256>>>(w_ao, waoT, CDIM, CDIM);
    transpose_kernel<<<dim3(C4 / 32, CDIM / 32, LAYERS), 256>>>(w_fc, wfcT, CDIM, C4);
    transpose_kernel<<<dim3(CDIM / 32, C4 / 32, LAYERS), 256>>>(w_fp, wfpT, C4, CDIM);

    embed_kernel<<<(MROWS * CDIM) / 256, 256>>>(idx, wte, wpe, x);

    for (int l = 0; l < LAYERS; l++) {
        ln_kernel<<<MROWS, 256>>>(x, ln1_w + l * CDIM, ln1_b + l * CDIM, hh);
        hgemm<3><<<dim3(C3 / 128, MROWS / 128), 128, HG_SMEM>>>(
            hh, wqkvT + (size_t)l * C3 * CDIM, b_qkv + l * C3, nullptr, qkvh,
            MROWS, C3, CDIM);
        attn_mma<<<dim3(TSEQ / 64, BATCH * HEADS), 128, AT_SMEM>>>(qkvh, yh);
        hgemm<1><<<dim3(CDIM / 128, MROWS / 128), 128, HG_SMEM>>>(
            yh, waoT + (size_t)l * CDIM * CDIM, b_ao + l * CDIM, x, x,
            MROWS, CDIM, CDIM);
        ln_kernel<<<MROWS, 256>>>(x, ln2_w + l * CDIM, ln2_b + l * CDIM, hh);
        hgemm<2><<<dim3(C4 / 128, MROWS / 128), 128, HG_SMEM>>>(
            hh, wfcT + (size_t)l * C4 * CDIM, b_fc + l * C4, nullptr, fch,
            MROWS, C4, CDIM);
        hgemm<1><<<dim3(CDIM / 128, MROWS / 128), 128, HG_SMEM>>>(
            fch, wfpT + (size_t)l * CDIM * C4, b_fp + l * CDIM, x, x,
            MROWS, CDIM, C4);
    }

    head_kernel<<<MROWS, 256>>>(x, lnf_w, lnf_b, w_head, out);
}